// round 14
// baseline (speedup 1.0000x reference)
#include <cuda_runtime.h>
#include <cuda_bf16.h>
#include <cstdint>

#define NN 100000
#define NE 1600000
#define FD 128
#define NC 40
#define SCAN_BLK 1024
#define NSCAN ((NN + SCAN_BLK - 1) / SCAN_BLK)   // 98
#define LN_EPS 1e-5f
#define NTILES ((NN + 63) / 64)                  // 1563
#define GEMM_GRID 296                            // 2 CTAs/SM * 148 SMs
#define AGG3_GRID 1184                           // persistent fused agg+proj

// ---------------- scratch (static device arrays; no allocation) ----------------
__device__ int   g_count[NN];
__device__ int   g_rowptr[NN + 1];
__device__ int   g_cursor[NN];
__device__ float g_dinv[NN];
__device__ int2  g_csr[NE];            // x = src, y = __float_as_int(w)
__device__ __nv_bfloat16 g_hAb[(size_t)NN * FD];   // gemm output, bf16 (agg operand)
__device__ float g_hB[(size_t)NN * FD];            // agg_ln output, fp32 (gemm2 input)
__device__ float g_h3[(size_t)NN * NC];
__device__ int   g_bsum[NSCAN];
__device__ int   g_boff[NSCAN];
// bf16-split W images, transposed: [n][k] row-major, k contiguous
__device__ __nv_bfloat16 g_W1hi[FD * FD];
__device__ __nv_bfloat16 g_W1lo[FD * FD];
__device__ __nv_bfloat16 g_W2hi[FD * FD];
__device__ __nv_bfloat16 g_W2lo[FD * FD];

// ---------------- helpers ----------------
__device__ __forceinline__ uint32_t smem_u32(const void* p) {
    uint32_t a;
    asm("{ .reg .u64 t; cvta.to.shared.u64 t, %1; cvt.u32.u64 %0, t; }" : "=r"(a) : "l"(p));
    return a;
}
__device__ __forceinline__ float2 ldbf2(const __nv_bfloat16* p) {
    __nv_bfloat162 raw = *(const __nv_bfloat162*)p;
    return __bfloat1622float2(raw);
}
#define LDSM_X4(r0, r1, r2, r3, addr) \
    asm volatile("ldmatrix.sync.aligned.m8n8.x4.shared.b16 {%0,%1,%2,%3}, [%4];" \
                 : "=r"(r0), "=r"(r1), "=r"(r2), "=r"(r3) : "r"(addr))
#define LDSM_X2(r0, r1, addr) \
    asm volatile("ldmatrix.sync.aligned.m8n8.x2.shared.b16 {%0,%1}, [%2];" \
                 : "=r"(r0), "=r"(r1) : "r"(addr))
#define MMA_BF16(d, a, b) \
    asm volatile("mma.sync.aligned.m16n8k16.row.col.f32.bf16.bf16.f32 " \
                 "{%0,%1,%2,%3}, {%4,%5,%6,%7}, {%8,%9}, {%0,%1,%2,%3};" \
                 : "+f"((d)[0]), "+f"((d)[1]), "+f"((d)[2]), "+f"((d)[3]) \
                 : "r"((a)[0]), "r"((a)[1]), "r"((a)[2]), "r"((a)[3]), \
                   "r"((b)[0]), "r"((b)[1]))

// smem tile geometry: bf16, row stride 136 elems (272B) -> conflict-free ldmatrix
#define TSTRIDE 136
#define ATILE_B (64 * TSTRIDE * 2)    // 17408 bytes (M=64)
#define BTILE_B (128 * TSTRIDE * 2)   // 34816 bytes
#define AHI_B   0
#define ALO_B   (ATILE_B)
#define BHI_B   (2 * ATILE_B)
#define BLO_B   (2 * ATILE_B + BTILE_B)
#define GM_SMEM (2 * ATILE_B + 2 * BTILE_B)   // 104448 bytes -> 2 CTAs/SM

// ---------------- fused setup: W1/W2 bf16 split + count zeroing ----------------
__global__ void k_setup(const float* __restrict__ W1, const float* __restrict__ W2) {
    int i = blockIdx.x * blockDim.x + threadIdx.x;
    if (i < FD * FD) {
        int k = i >> 7, n = i & 127;
        float v1 = W1[i];
        __nv_bfloat16 h1 = __float2bfloat16_rn(v1);
        g_W1hi[n * FD + k] = h1;
        g_W1lo[n * FD + k] = __float2bfloat16_rn(v1 - __bfloat162float(h1));
        float v2 = W2[i];
        __nv_bfloat16 h2 = __float2bfloat16_rn(v2);
        g_W2hi[n * FD + k] = h2;
        g_W2lo[n * FD + k] = __float2bfloat16_rn(v2 - __bfloat162float(h2));
    }
    if (i < NN) g_count[i] = 0;
}

// ---------------- persistent tensor-core GEMM: C_bf16[N,128] = A[N,128] @ W ----------------
__device__ __forceinline__ void load_A_regs(float4 (&buf)[8], const float* __restrict__ A,
                                            int r0, int tid) {
#pragma unroll
    for (int i = 0; i < 8; i++) {
        int idx = tid + i * 256;
        int row = idx >> 5;
        int c = (idx & 31) * 4;
        int gr = r0 + row;
        buf[i] = (gr < NN) ? *(const float4*)(A + (size_t)gr * FD + c)
                           : make_float4(0.f, 0.f, 0.f, 0.f);
    }
}

__global__ void __launch_bounds__(256, 2) k_gemm_tc(const float* __restrict__ A,
                                                    const __nv_bfloat16* __restrict__ Whi,
                                                    const __nv_bfloat16* __restrict__ Wlo,
                                                    __nv_bfloat16* __restrict__ C) {
    extern __shared__ char smem[];
    uint32_t sb = smem_u32(smem);
    int tid = threadIdx.x;
    int wid = tid >> 5, lane = tid & 31;

    // ---- stage W once (hi/lo): [n][k], stride 136 ----
    {
        const uint4* sh = (const uint4*)Whi;
        const uint4* sl = (const uint4*)Wlo;
        for (int i = tid; i < 2048; i += 256) {
            int n = i >> 4, kg = (i & 15) * 8;
            *(uint4*)(smem + BHI_B + (n * TSTRIDE + kg) * 2) = sh[i];
            *(uint4*)(smem + BLO_B + (n * TSTRIDE + kg) * 2) = sl[i];
        }
    }

    int warpRow = wid >> 2;
    int warpCol = wid & 3;
    uint32_t aoff = ((warpRow * 32 + (lane & 15)) * TSTRIDE + (lane >> 4) * 8) * 2;
    uint32_t aHiB = sb + AHI_B + aoff;
    uint32_t aLoB = sb + ALO_B + aoff;
    uint32_t boff = ((warpCol * 32 + (lane & 7)) * TSTRIDE + ((lane >> 3) & 1) * 8) * 2;
    uint32_t bHiB = sb + BHI_B + boff;
    uint32_t bLoB = sb + BLO_B + boff;
    int gid = lane >> 2, tg = lane & 3;

    int t = blockIdx.x;
    float4 buf[8];
    if (t < NTILES) load_A_regs(buf, A, t * 64, tid);

    for (; t < NTILES; t += GEMM_GRID) {
        int r0 = t * 64;
        __syncthreads();

#pragma unroll
        for (int i = 0; i < 8; i++) {
            int idx = tid + i * 256;
            int row = idx >> 5;
            int c = (idx & 31) * 4;
            float4 v = buf[i];
            __nv_bfloat16 h0 = __float2bfloat16_rn(v.x), h1 = __float2bfloat16_rn(v.y);
            __nv_bfloat16 h2 = __float2bfloat16_rn(v.z), h3 = __float2bfloat16_rn(v.w);
            __nv_bfloat16 l0 = __float2bfloat16_rn(v.x - __bfloat162float(h0));
            __nv_bfloat16 l1 = __float2bfloat16_rn(v.y - __bfloat162float(h1));
            __nv_bfloat16 l2 = __float2bfloat16_rn(v.z - __bfloat162float(h2));
            __nv_bfloat16 l3 = __float2bfloat16_rn(v.w - __bfloat162float(h3));
            uint32_t hp0 = (uint32_t)__bfloat16_as_ushort(h0) | ((uint32_t)__bfloat16_as_ushort(h1) << 16);
            uint32_t hp1 = (uint32_t)__bfloat16_as_ushort(h2) | ((uint32_t)__bfloat16_as_ushort(h3) << 16);
            uint32_t lp0 = (uint32_t)__bfloat16_as_ushort(l0) | ((uint32_t)__bfloat16_as_ushort(l1) << 16);
            uint32_t lp1 = (uint32_t)__bfloat16_as_ushort(l2) | ((uint32_t)__bfloat16_as_ushort(l3) << 16);
            uint32_t off = (row * TSTRIDE + c) * 2;
            *(uint2*)(smem + AHI_B + off) = make_uint2(hp0, hp1);
            *(uint2*)(smem + ALO_B + off) = make_uint2(lp0, lp1);
        }
        __syncthreads();

        int tn = t + GEMM_GRID;
        if (tn < NTILES) load_A_regs(buf, A, tn * 64, tid);

        float acc[2][4][4];
#pragma unroll
        for (int mi = 0; mi < 2; mi++)
#pragma unroll
            for (int nj = 0; nj < 4; nj++)
#pragma unroll
                for (int q = 0; q < 4; q++) acc[mi][nj][q] = 0.f;

#pragma unroll
        for (int kt = 0; kt < 8; kt++) {
            uint32_t ka = kt * 32;
            uint32_t ah[2][4], al[2][4], bh[4][2], bl[4][2];
#pragma unroll
            for (int mi = 0; mi < 2; mi++) {
                uint32_t d = mi * (16 * TSTRIDE * 2) + ka;
                LDSM_X4(ah[mi][0], ah[mi][1], ah[mi][2], ah[mi][3], aHiB + d);
                LDSM_X4(al[mi][0], al[mi][1], al[mi][2], al[mi][3], aLoB + d);
            }
#pragma unroll
            for (int nj = 0; nj < 4; nj++) {
                uint32_t d = nj * (8 * TSTRIDE * 2) + ka;
                LDSM_X2(bh[nj][0], bh[nj][1], bHiB + d);
                LDSM_X2(bl[nj][0], bl[nj][1], bLoB + d);
            }
#pragma unroll
            for (int mi = 0; mi < 2; mi++)
#pragma unroll
                for (int nj = 0; nj < 4; nj++) {
                    MMA_BF16(acc[mi][nj], ah[mi], bh[nj]);
                    MMA_BF16(acc[mi][nj], ah[mi], bl[nj]);
                    MMA_BF16(acc[mi][nj], al[mi], bh[nj]);
                }
        }

#pragma unroll
        for (int mi = 0; mi < 2; mi++) {
            int r = r0 + warpRow * 32 + mi * 16 + gid;
#pragma unroll
            for (int nj = 0; nj < 4; nj++) {
                int cb = warpCol * 32 + nj * 8 + tg * 2;
                if (r < NN) {
                    __nv_bfloat162 v;
                    v.x = __float2bfloat16_rn(acc[mi][nj][0]);
                    v.y = __float2bfloat16_rn(acc[mi][nj][1]);
                    *(__nv_bfloat162*)(C + (size_t)r * FD + cb) = v;
                }
                if (r + 8 < NN) {
                    __nv_bfloat162 v;
                    v.x = __float2bfloat16_rn(acc[mi][nj][2]);
                    v.y = __float2bfloat16_rn(acc[mi][nj][3]);
                    *(__nv_bfloat162*)(C + (size_t)(r + 8) * FD + cb) = v;
                }
            }
        }
    }
}

// ---------------- CSR build ----------------
__global__ void k_hist(const int4* __restrict__ dst4) {
    int e4 = blockIdx.x * blockDim.x + threadIdx.x;
    if (e4 >= NE / 4) return;
    int4 d = dst4[e4];
    atomicAdd(&g_count[d.x], 1);
    atomicAdd(&g_count[d.y], 1);
    atomicAdd(&g_count[d.z], 1);
    atomicAdd(&g_count[d.w], 1);
}

__global__ void k_scanA() {
    __shared__ int sh[SCAN_BLK];
    int i = blockIdx.x * SCAN_BLK + threadIdx.x;
    int v = (i < NN) ? g_count[i] : 0;
    if (i < NN) g_dinv[i] = rsqrtf((float)(v + 1));   // +1 self-loop
    sh[threadIdx.x] = v;
    __syncthreads();
    for (int off = SCAN_BLK / 2; off > 0; off >>= 1) {
        if (threadIdx.x < off) sh[threadIdx.x] += sh[threadIdx.x + off];
        __syncthreads();
    }
    if (threadIdx.x == 0) g_bsum[blockIdx.x] = sh[0];
}

__global__ void k_scanB() {
    __shared__ int sh[NSCAN];
    if (threadIdx.x < NSCAN) sh[threadIdx.x] = g_bsum[threadIdx.x];
    __syncthreads();
    if (threadIdx.x == 0) {
        int run = 0;
        for (int b = 0; b < NSCAN; b++) { int t = sh[b]; sh[b] = run; run += t; }
        g_rowptr[NN] = run;
    }
    __syncthreads();
    if (threadIdx.x < NSCAN) g_boff[threadIdx.x] = sh[threadIdx.x];
}

__global__ void k_scanC() {
    __shared__ int sh[SCAN_BLK];
    int i = blockIdx.x * SCAN_BLK + threadIdx.x;
    int v = (i < NN) ? g_count[i] : 0;
    sh[threadIdx.x] = v;
    __syncthreads();
    for (int off = 1; off < SCAN_BLK; off <<= 1) {
        int t = (threadIdx.x >= off) ? sh[threadIdx.x - off] : 0;
        __syncthreads();
        sh[threadIdx.x] += t;
        __syncthreads();
    }
    if (i < NN) {
        int excl = sh[threadIdx.x] - v + g_boff[blockIdx.x];
        g_rowptr[i] = excl;
        g_cursor[i] = excl;
    }
}

__global__ void k_fill(const int4* __restrict__ src4, const int4* __restrict__ dst4) {
    int e4 = blockIdx.x * blockDim.x + threadIdx.x;
    if (e4 >= NE / 4) return;
    int4 s = src4[e4];
    int4 d = dst4[e4];
    int ss[4] = {s.x, s.y, s.z, s.w};
    int dd[4] = {d.x, d.y, d.z, d.w};
#pragma unroll
    for (int q = 0; q < 4; q++) {
        int idx = atomicAdd(&g_cursor[dd[q]], 1);
        g_csr[idx] = make_int2(ss[q], __float_as_int(g_dinv[ss[q]] * g_dinv[dd[q]]));
    }
}

// ---------------- half-row agg core: 2 warps per node, 64 cols (2/lane) each ----------------
// Returns per-lane x (post-bias, pre-LN) pair; LN reduction done by caller via smem.
__device__ __forceinline__ float2 agg_half(const __nv_bfloat16* __restrict__ h,
                                           const float* __restrict__ bias,
                                           int node, int c0) {
    float dn = g_dinv[node];
    float sw = dn * dn;
    float2 hv = ldbf2(h + (size_t)node * FD + c0);
    float a0 = sw * hv.x, a1 = sw * hv.y;

    int e   = g_rowptr[node];
    int end = g_rowptr[node + 1];
    for (; e + 8 <= end; e += 8) {
        int2 p[8];
#pragma unroll
        for (int q = 0; q < 8; q++) p[q] = __ldcs(&g_csr[e + q]);
        float2 v_[8];
#pragma unroll
        for (int q = 0; q < 8; q++) v_[q] = ldbf2(h + (size_t)p[q].x * FD + c0);
#pragma unroll
        for (int q = 0; q < 8; q++) {
            float w = __int_as_float(p[q].y);
            a0 = fmaf(w, v_[q].x, a0);
            a1 = fmaf(w, v_[q].y, a1);
        }
    }
    for (; e + 2 <= end; e += 2) {
        int2 p0 = __ldcs(&g_csr[e]), p1 = __ldcs(&g_csr[e + 1]);
        float2 v0 = ldbf2(h + (size_t)p0.x * FD + c0);
        float2 v1 = ldbf2(h + (size_t)p1.x * FD + c0);
        float w0 = __int_as_float(p0.y), w1 = __int_as_float(p1.y);
        a0 += w0 * v0.x + w1 * v1.x;
        a1 += w0 * v0.y + w1 * v1.y;
    }
    if (e < end) {
        int2 p = __ldcs(&g_csr[e]);
        float w = __int_as_float(p.y);
        float2 v = ldbf2(h + (size_t)p.x * FD + c0);
        a0 += w * v.x; a1 += w * v.y;
    }
    return make_float2(a0 + bias[c0], a1 + bias[c0 + 1]);
}

__device__ __forceinline__ float warp_sum(float v) {
#pragma unroll
    for (int o = 16; o > 0; o >>= 1) v += __shfl_xor_sync(0xffffffffu, v, o);
    return v;
}

// ---------------- layer-1 aggregation: 2 warps/node, 4 nodes per 256-thr block --------------
__global__ void __launch_bounds__(256) k_agg_ln(const __nv_bfloat16* __restrict__ h,
                                                const float* __restrict__ bias,
                                                const float* __restrict__ gamma,
                                                const float* __restrict__ beta,
                                                float* __restrict__ out) {
    __shared__ float sred[8];
    int tid = threadIdx.x;
    int wid = tid >> 5, lane = tid & 31;
    int g = wid >> 1, sub = wid & 1;
    int node = blockIdx.x * 4 + g;            // NN % 4 == 0 -> no tail
    int c0 = sub * 64 + lane * 2;

    float2 x = agg_half(h, bias, node, c0);

    float s = warp_sum(x.x + x.y);
    if (lane == 0) sred[wid] = s;
    __syncthreads();
    float mean = (sred[g * 2] + sred[g * 2 + 1]) * (1.f / FD);
    __syncthreads();

    float d0 = x.x - mean, d1 = x.y - mean;
    float ss = warp_sum(d0 * d0 + d1 * d1);
    if (lane == 0) sred[wid] = ss;
    __syncthreads();
    float inv = rsqrtf((sred[g * 2] + sred[g * 2 + 1]) * (1.f / FD) + LN_EPS);

    float2 gm = *(const float2*)(gamma + c0);
    float2 bt = *(const float2*)(beta + c0);
    float2 y;
    y.x = fmaxf(d0 * inv * gm.x + bt.x, 0.f);
    y.y = fmaxf(d1 * inv * gm.y + bt.y, 0.f);
    *(float2*)(out + (size_t)node * FD + c0) = y;
}

// ---------------- layer-2 agg + projection: persistent, 2 warps/node ----------------
__global__ void __launch_bounds__(256) k_agg_ln_proj(const __nv_bfloat16* __restrict__ h,
                                                     const float* __restrict__ bias,
                                                     const float* __restrict__ gamma,
                                                     const float* __restrict__ beta,
                                                     const float* __restrict__ W3,
                                                     float* __restrict__ h3out) {
    __shared__ float Ws[FD * NC];          // 20 KB, staged ONCE per CTA
    __shared__ float rbuf[4][FD];          // 2 KB
    __shared__ float sred[8];
    int tid = threadIdx.x;
    for (int i = tid; i < FD * NC; i += 256) Ws[i] = W3[i];
    __syncthreads();

    int wid = tid >> 5, lane = tid & 31;
    int g = wid >> 1, sub = wid & 1;
    int c0 = sub * 64 + lane * 2;
    int c1 = 32 + (lane & 7);

    for (int base = blockIdx.x * 4; base < NN; base += AGG3_GRID * 4) {
        int gw = base + g;
        bool valid = gw < NN;

        float2 x = make_float2(0.f, 0.f);
        if (valid) x = agg_half(h, bias, gw, c0);

        float s = warp_sum(x.x + x.y);
        if (lane == 0) sred[wid] = s;
        __syncthreads();
        float mean = (sred[g * 2] + sred[g * 2 + 1]) * (1.f / FD);
        __syncthreads();

        float d0 = x.x - mean, d1 = x.y - mean;
        float ss = warp_sum(d0 * d0 + d1 * d1);
        if (lane == 0) sred[wid] = ss;
        __syncthreads();
        float inv = rsqrtf((sred[g * 2] + sred[g * 2 + 1]) * (1.f / FD) + LN_EPS);

        float2 gm = *(const float2*)(gamma + c0);
        float2 bt = *(const float2*)(beta + c0);
        rbuf[g][c0]     = fmaxf(d0 * inv * gm.x + bt.x, 0.f);
        rbuf[g][c0 + 1] = fmaxf(d1 * inv * gm.y + bt.y, 0.f);
        __syncthreads();

        if (valid && sub == 0) {
            float acc0 = 0.f, acc1 = 0.f;
#pragma unroll
            for (int k = 0; k < FD; k++) {
                float xk = rbuf[g][k];
                acc0 = fmaf(xk, Ws[k * NC + lane], acc0);
                acc1 = fmaf(xk, Ws[k * NC + c1], acc1);
            }
            h3out[(size_t)gw * NC + lane] = acc0;
            if (lane < 8) h3out[(size_t)gw * NC + 32 + lane] = acc1;
        }
        __syncthreads();
    }
}

// ---------------- output aggregation + bias + log_softmax ----------------
__global__ void __launch_bounds__(256) k_agg_out(const float* __restrict__ h3,
                                                 const float* __restrict__ b3,
                                                 float* __restrict__ out) {
    int gw = (blockIdx.x * blockDim.x + threadIdx.x) >> 5;
    if (gw >= NN) return;
    int lane = threadIdx.x & 31;
    int node = gw;
    bool hi = lane < (NC - 32);
    int c1 = 32 + (lane & 7);

    float dn = g_dinv[node];
    float sw = dn * dn;
    float a0 = sw * __ldg(&h3[(size_t)node * NC + lane]);
    float a1 = sw * __ldg(&h3[(size_t)node * NC + c1]);

    int e   = g_rowptr[node];
    int end = g_rowptr[node + 1];
    for (; e + 4 <= end; e += 4) {
        int2 p[4];
#pragma unroll
        for (int q = 0; q < 4; q++) p[q] = __ldcs(&g_csr[e + q]);
        float v0[4], v1[4];
#pragma unroll
        for (int q = 0; q < 4; q++) {
            v0[q] = __ldg(&h3[(size_t)p[q].x * NC + lane]);
            v1[q] = __ldg(&h3[(size_t)p[q].x * NC + c1]);
        }
#pragma unroll
        for (int q = 0; q < 4; q++) {
            float w = __int_as_float(p[q].y);
            a0 = fmaf(w, v0[q], a0);
            a1 = fmaf(w, v1[q], a1);
        }
    }
    for (; e < end; e++) {
        int2 p = __ldcs(&g_csr[e]);
        float w = __int_as_float(p.y);
        a0 = fmaf(w, __ldg(&h3[(size_t)p.x * NC + lane]), a0);
        a1 = fmaf(w, __ldg(&h3[(size_t)p.x * NC + c1]), a1);
    }

    float x0 = a0 + b3[lane];
    float x1 = hi ? (a1 + b3[32 + lane]) : -1e30f;

    float m = fmaxf(x0, x1);
#pragma unroll
    for (int o = 16; o > 0; o >>= 1) m = fmaxf(m, __shfl_xor_sync(0xffffffffu, m, o));
    float se = __expf(x0 - m) + (hi ? __expf(x1 - m) : 0.f);
#pragma unroll
    for (int o = 16; o > 0; o >>= 1) se += __shfl_xor_sync(0xffffffffu, se, o);
    float L = m + __logf(se);

    out[(size_t)node * NC + lane] = x0 - L;
    if (hi) out[(size_t)node * NC + 32 + lane] = x1 - L;
}

// ---------------- launch ----------------
extern "C" void kernel_launch(void* const* d_in, const int* in_sizes, int n_in,
                              void* d_out, int out_size) {
    const float* x    = (const float*)d_in[0];
    const int*   ei   = (const int*)d_in[1];
    const float* W1   = (const float*)d_in[2];
    const float* b1   = (const float*)d_in[3];
    const float* g1   = (const float*)d_in[4];
    const float* be1  = (const float*)d_in[5];
    const float* W2   = (const float*)d_in[6];
    const float* b2   = (const float*)d_in[7];
    const float* g2   = (const float*)d_in[8];
    const float* be2  = (const float*)d_in[9];
    const float* W3   = (const float*)d_in[10];
    const float* b3   = (const float*)d_in[11];
    float* out = (float*)d_out;

    const int4* src4 = (const int4*)ei;
    const int4* dst4 = (const int4*)(ei + NE);

    float *hB, *h3;
    __nv_bfloat16 *hAb, *w1h, *w1l, *w2h, *w2l;
    cudaGetSymbolAddress((void**)&hAb, g_hAb);
    cudaGetSymbolAddress((void**)&hB, g_hB);
    cudaGetSymbolAddress((void**)&h3, g_h3);
    cudaGetSymbolAddress((void**)&w1h, g_W1hi);
    cudaGetSymbolAddress((void**)&w1l, g_W1lo);
    cudaGetSymbolAddress((void**)&w2h, g_W2hi);
    cudaGetSymbolAddress((void**)&w2l, g_W2lo);
    (void)n_in; (void)in_sizes; (void)out_size;

    cudaFuncSetAttribute(k_gemm_tc, cudaFuncAttributeMaxDynamicSharedMemorySize, GM_SMEM);

    int tE4 = (NE / 4 + 255) / 256;
    int gWarp = (NN * 32 + 255) / 256;
    int gSetup = (NN + 255) / 256;
    int gAgg = NN / 4;   // 25000, 2 warps/node

    // 10 launches
    k_setup<<<gSetup, 256>>>(W1, W2);
    k_gemm_tc<<<GEMM_GRID, 256, GM_SMEM>>>(x, w1h, w1l, hAb);
    k_hist<<<tE4, 256>>>(dst4);
    k_scanA<<<NSCAN, SCAN_BLK>>>();
    k_scanB<<<1, 128>>>();
    k_scanC<<<NSCAN, SCAN_BLK>>>();
    k_fill<<<tE4, 256>>>(src4, dst4);

    // layer 1 aggregation (bf16 operand, fp32 out, 2 warps/node)
    k_agg_ln<<<gAgg, 256>>>(hAb, b1, g1, be1, hB);
    // layer 2 gemm (fp32 in, bf16 out)
    k_gemm_tc<<<GEMM_GRID, 256, GM_SMEM>>>(hB, w2h, w2l, hAb);
    // layer 2 aggregation fused with W3 projection (persistent, 2 warps/node)
    k_agg_ln_proj<<<AGG3_GRID, 256>>>(hAb, b2, g2, be2, W3, h3);
    // output aggregation + log_softmax
    k_agg_out<<<gWarp, 256>>>(h3, b3, out);
}

// round 15
// speedup vs baseline: 1.1674x; 1.1674x over previous
#include <cuda_runtime.h>
#include <cuda_bf16.h>
#include <cstdint>

#define NN 100000
#define NE 1600000
#define FD 128
#define NC 40
#define SCAN_BLK 1024
#define NSCAN ((NN + SCAN_BLK - 1) / SCAN_BLK)   // 98
#define LN_EPS 1e-5f
#define NTILES ((NN + 63) / 64)                  // 1563
#define GEMM_GRID 296                            // 2 CTAs/SM * 148 SMs
#define AGG3_GRID 1184                           // persistent fused agg+proj

// ---------------- scratch (static device arrays; no allocation) ----------------
__device__ int   g_count[NN];
__device__ int   g_rowptr[NN + 1];
__device__ int   g_cursor[NN];
__device__ float g_dinv[NN];
__device__ int2  g_csr[NE];            // x = src, y = __float_as_int(w)
__device__ __nv_bfloat16 g_hAb[(size_t)NN * FD];   // gemm output, bf16 (agg operand)
__device__ float g_hB[(size_t)NN * FD];            // agg_ln output, fp32 (gemm2 input)
__device__ float g_h3[(size_t)NN * NC];
__device__ int   g_bsum[NSCAN];
__device__ int   g_boff[NSCAN];
// bf16-split W images, transposed: [n][k] row-major, k contiguous
__device__ __nv_bfloat16 g_W1hi[FD * FD];
__device__ __nv_bfloat16 g_W1lo[FD * FD];
__device__ __nv_bfloat16 g_W2hi[FD * FD];
__device__ __nv_bfloat16 g_W2lo[FD * FD];

// ---------------- helpers ----------------
__device__ __forceinline__ uint32_t smem_u32(const void* p) {
    uint32_t a;
    asm("{ .reg .u64 t; cvta.to.shared.u64 t, %1; cvt.u32.u64 %0, t; }" : "=r"(a) : "l"(p));
    return a;
}
// load 4 consecutive bf16 (8B aligned) -> float4
__device__ __forceinline__ float4 ldbf4(const __nv_bfloat16* p) {
    uint2 raw = *(const uint2*)p;
    __nv_bfloat162 a = *reinterpret_cast<__nv_bfloat162*>(&raw.x);
    __nv_bfloat162 b = *reinterpret_cast<__nv_bfloat162*>(&raw.y);
    float2 fa = __bfloat1622float2(a);
    float2 fb = __bfloat1622float2(b);
    return make_float4(fa.x, fa.y, fb.x, fb.y);
}
#define LDSM_X4(r0, r1, r2, r3, addr) \
    asm volatile("ldmatrix.sync.aligned.m8n8.x4.shared.b16 {%0,%1,%2,%3}, [%4];" \
                 : "=r"(r0), "=r"(r1), "=r"(r2), "=r"(r3) : "r"(addr))
#define LDSM_X2(r0, r1, addr) \
    asm volatile("ldmatrix.sync.aligned.m8n8.x2.shared.b16 {%0,%1}, [%2];" \
                 : "=r"(r0), "=r"(r1) : "r"(addr))
#define MMA_BF16(d, a, b) \
    asm volatile("mma.sync.aligned.m16n8k16.row.col.f32.bf16.bf16.f32 " \
                 "{%0,%1,%2,%3}, {%4,%5,%6,%7}, {%8,%9}, {%0,%1,%2,%3};" \
                 : "+f"((d)[0]), "+f"((d)[1]), "+f"((d)[2]), "+f"((d)[3]) \
                 : "r"((a)[0]), "r"((a)[1]), "r"((a)[2]), "r"((a)[3]), \
                   "r"((b)[0]), "r"((b)[1]))

// smem tile geometry: bf16, row stride 136 elems (272B) -> conflict-free ldmatrix
#define TSTRIDE 136
#define ATILE_B (64 * TSTRIDE * 2)    // 17408 bytes (M=64)
#define BTILE_B (128 * TSTRIDE * 2)   // 34816 bytes
#define AHI_B   0
#define ALO_B   (ATILE_B)
#define BHI_B   (2 * ATILE_B)
#define BLO_B   (2 * ATILE_B + BTILE_B)
#define GM_SMEM (2 * ATILE_B + 2 * BTILE_B)   // 104448 bytes -> 2 CTAs/SM

// ---------------- fused setup: W1/W2 bf16 split + count zeroing ----------------
__global__ void k_setup(const float* __restrict__ W1, const float* __restrict__ W2) {
    int i = blockIdx.x * blockDim.x + threadIdx.x;
    if (i < FD * FD) {
        int k = i >> 7, n = i & 127;
        float v1 = W1[i];
        __nv_bfloat16 h1 = __float2bfloat16_rn(v1);
        g_W1hi[n * FD + k] = h1;
        g_W1lo[n * FD + k] = __float2bfloat16_rn(v1 - __bfloat162float(h1));
        float v2 = W2[i];
        __nv_bfloat16 h2 = __float2bfloat16_rn(v2);
        g_W2hi[n * FD + k] = h2;
        g_W2lo[n * FD + k] = __float2bfloat16_rn(v2 - __bfloat162float(h2));
    }
    if (i < NN) g_count[i] = 0;
}

// ---------------- persistent tensor-core GEMM: C_bf16[N,128] = A[N,128] @ W ----------------
__device__ __forceinline__ void load_A_regs(float4 (&buf)[8], const float* __restrict__ A,
                                            int r0, int tid) {
#pragma unroll
    for (int i = 0; i < 8; i++) {
        int idx = tid + i * 256;
        int row = idx >> 5;
        int c = (idx & 31) * 4;
        int gr = r0 + row;
        buf[i] = (gr < NN) ? *(const float4*)(A + (size_t)gr * FD + c)
                           : make_float4(0.f, 0.f, 0.f, 0.f);
    }
}

__global__ void __launch_bounds__(256, 2) k_gemm_tc(const float* __restrict__ A,
                                                    const __nv_bfloat16* __restrict__ Whi,
                                                    const __nv_bfloat16* __restrict__ Wlo,
                                                    __nv_bfloat16* __restrict__ C) {
    extern __shared__ char smem[];
    uint32_t sb = smem_u32(smem);
    int tid = threadIdx.x;
    int wid = tid >> 5, lane = tid & 31;

    // ---- stage W once (hi/lo): [n][k], stride 136 ----
    {
        const uint4* sh = (const uint4*)Whi;
        const uint4* sl = (const uint4*)Wlo;
        for (int i = tid; i < 2048; i += 256) {
            int n = i >> 4, kg = (i & 15) * 8;
            *(uint4*)(smem + BHI_B + (n * TSTRIDE + kg) * 2) = sh[i];
            *(uint4*)(smem + BLO_B + (n * TSTRIDE + kg) * 2) = sl[i];
        }
    }

    int warpRow = wid >> 2;
    int warpCol = wid & 3;
    uint32_t aoff = ((warpRow * 32 + (lane & 15)) * TSTRIDE + (lane >> 4) * 8) * 2;
    uint32_t aHiB = sb + AHI_B + aoff;
    uint32_t aLoB = sb + ALO_B + aoff;
    uint32_t boff = ((warpCol * 32 + (lane & 7)) * TSTRIDE + ((lane >> 3) & 1) * 8) * 2;
    uint32_t bHiB = sb + BHI_B + boff;
    uint32_t bLoB = sb + BLO_B + boff;
    int gid = lane >> 2, tg = lane & 3;

    int t = blockIdx.x;
    float4 buf[8];
    if (t < NTILES) load_A_regs(buf, A, t * 64, tid);

    for (; t < NTILES; t += GEMM_GRID) {
        int r0 = t * 64;
        __syncthreads();

#pragma unroll
        for (int i = 0; i < 8; i++) {
            int idx = tid + i * 256;
            int row = idx >> 5;
            int c = (idx & 31) * 4;
            float4 v = buf[i];
            __nv_bfloat16 h0 = __float2bfloat16_rn(v.x), h1 = __float2bfloat16_rn(v.y);
            __nv_bfloat16 h2 = __float2bfloat16_rn(v.z), h3 = __float2bfloat16_rn(v.w);
            __nv_bfloat16 l0 = __float2bfloat16_rn(v.x - __bfloat162float(h0));
            __nv_bfloat16 l1 = __float2bfloat16_rn(v.y - __bfloat162float(h1));
            __nv_bfloat16 l2 = __float2bfloat16_rn(v.z - __bfloat162float(h2));
            __nv_bfloat16 l3 = __float2bfloat16_rn(v.w - __bfloat162float(h3));
            uint32_t hp0 = (uint32_t)__bfloat16_as_ushort(h0) | ((uint32_t)__bfloat16_as_ushort(h1) << 16);
            uint32_t hp1 = (uint32_t)__bfloat16_as_ushort(h2) | ((uint32_t)__bfloat16_as_ushort(h3) << 16);
            uint32_t lp0 = (uint32_t)__bfloat16_as_ushort(l0) | ((uint32_t)__bfloat16_as_ushort(l1) << 16);
            uint32_t lp1 = (uint32_t)__bfloat16_as_ushort(l2) | ((uint32_t)__bfloat16_as_ushort(l3) << 16);
            uint32_t off = (row * TSTRIDE + c) * 2;
            *(uint2*)(smem + AHI_B + off) = make_uint2(hp0, hp1);
            *(uint2*)(smem + ALO_B + off) = make_uint2(lp0, lp1);
        }
        __syncthreads();

        int tn = t + GEMM_GRID;
        if (tn < NTILES) load_A_regs(buf, A, tn * 64, tid);

        float acc[2][4][4];
#pragma unroll
        for (int mi = 0; mi < 2; mi++)
#pragma unroll
            for (int nj = 0; nj < 4; nj++)
#pragma unroll
                for (int q = 0; q < 4; q++) acc[mi][nj][q] = 0.f;

#pragma unroll
        for (int kt = 0; kt < 8; kt++) {
            uint32_t ka = kt * 32;
            uint32_t ah[2][4], al[2][4], bh[4][2], bl[4][2];
#pragma unroll
            for (int mi = 0; mi < 2; mi++) {
                uint32_t d = mi * (16 * TSTRIDE * 2) + ka;
                LDSM_X4(ah[mi][0], ah[mi][1], ah[mi][2], ah[mi][3], aHiB + d);
                LDSM_X4(al[mi][0], al[mi][1], al[mi][2], al[mi][3], aLoB + d);
            }
#pragma unroll
            for (int nj = 0; nj < 4; nj++) {
                uint32_t d = nj * (8 * TSTRIDE * 2) + ka;
                LDSM_X2(bh[nj][0], bh[nj][1], bHiB + d);
                LDSM_X2(bl[nj][0], bl[nj][1], bLoB + d);
            }
#pragma unroll
            for (int mi = 0; mi < 2; mi++)
#pragma unroll
                for (int nj = 0; nj < 4; nj++) {
                    MMA_BF16(acc[mi][nj], ah[mi], bh[nj]);
                    MMA_BF16(acc[mi][nj], ah[mi], bl[nj]);
                    MMA_BF16(acc[mi][nj], al[mi], bh[nj]);
                }
        }

#pragma unroll
        for (int mi = 0; mi < 2; mi++) {
            int r = r0 + warpRow * 32 + mi * 16 + gid;
#pragma unroll
            for (int nj = 0; nj < 4; nj++) {
                int cb = warpCol * 32 + nj * 8 + tg * 2;
                if (r < NN) {
                    __nv_bfloat162 v;
                    v.x = __float2bfloat16_rn(acc[mi][nj][0]);
                    v.y = __float2bfloat16_rn(acc[mi][nj][1]);
                    *(__nv_bfloat162*)(C + (size_t)r * FD + cb) = v;
                }
                if (r + 8 < NN) {
                    __nv_bfloat162 v;
                    v.x = __float2bfloat16_rn(acc[mi][nj][2]);
                    v.y = __float2bfloat16_rn(acc[mi][nj][3]);
                    *(__nv_bfloat162*)(C + (size_t)(r + 8) * FD + cb) = v;
                }
            }
        }
    }
}

// ---------------- CSR build ----------------
__global__ void k_hist(const int4* __restrict__ dst4) {
    int e4 = blockIdx.x * blockDim.x + threadIdx.x;
    if (e4 >= NE / 4) return;
    int4 d = dst4[e4];
    atomicAdd(&g_count[d.x], 1);
    atomicAdd(&g_count[d.y], 1);
    atomicAdd(&g_count[d.z], 1);
    atomicAdd(&g_count[d.w], 1);
}

__global__ void k_scanA() {
    __shared__ int sh[SCAN_BLK];
    int i = blockIdx.x * SCAN_BLK + threadIdx.x;
    int v = (i < NN) ? g_count[i] : 0;
    if (i < NN) g_dinv[i] = rsqrtf((float)(v + 1));   // +1 self-loop
    sh[threadIdx.x] = v;
    __syncthreads();
    for (int off = SCAN_BLK / 2; off > 0; off >>= 1) {
        if (threadIdx.x < off) sh[threadIdx.x] += sh[threadIdx.x + off];
        __syncthreads();
    }
    if (threadIdx.x == 0) g_bsum[blockIdx.x] = sh[0];
}

__global__ void k_scanB() {
    __shared__ int sh[NSCAN];
    if (threadIdx.x < NSCAN) sh[threadIdx.x] = g_bsum[threadIdx.x];
    __syncthreads();
    if (threadIdx.x == 0) {
        int run = 0;
        for (int b = 0; b < NSCAN; b++) { int t = sh[b]; sh[b] = run; run += t; }
        g_rowptr[NN] = run;
    }
    __syncthreads();
    if (threadIdx.x < NSCAN) g_boff[threadIdx.x] = sh[threadIdx.x];
}

__global__ void k_scanC() {
    __shared__ int sh[SCAN_BLK];
    int i = blockIdx.x * SCAN_BLK + threadIdx.x;
    int v = (i < NN) ? g_count[i] : 0;
    sh[threadIdx.x] = v;
    __syncthreads();
    for (int off = 1; off < SCAN_BLK; off <<= 1) {
        int t = (threadIdx.x >= off) ? sh[threadIdx.x - off] : 0;
        __syncthreads();
        sh[threadIdx.x] += t;
        __syncthreads();
    }
    if (i < NN) {
        int excl = sh[threadIdx.x] - v + g_boff[blockIdx.x];
        g_rowptr[i] = excl;
        g_cursor[i] = excl;
    }
}

__global__ void k_fill(const int4* __restrict__ src4, const int4* __restrict__ dst4) {
    int e4 = blockIdx.x * blockDim.x + threadIdx.x;
    if (e4 >= NE / 4) return;
    int4 s = src4[e4];
    int4 d = dst4[e4];
    int ss[4] = {s.x, s.y, s.z, s.w};
    int dd[4] = {d.x, d.y, d.z, d.w};
#pragma unroll
    for (int q = 0; q < 4; q++) {
        int idx = atomicAdd(&g_cursor[dd[q]], 1);
        g_csr[idx] = make_int2(ss[q], __float_as_int(g_dinv[ss[q]] * g_dinv[dd[q]]));
    }
}

// ---------------- agg + bias + LN + ReLU core over bf16 h (returns y in float4) -------------
__device__ __forceinline__ float4 agg_ln_core(const __nv_bfloat16* __restrict__ h,
                                              const float* __restrict__ bias,
                                              const float* __restrict__ gamma,
                                              const float* __restrict__ beta,
                                              int node, int lane) {
    int c0 = lane * 4;
    float dn = g_dinv[node];
    float sw = dn * dn;
    float4 hv = ldbf4(h + (size_t)node * FD + c0);
    float ax = sw * hv.x, ay = sw * hv.y, az = sw * hv.z, aw = sw * hv.w;

    int e   = g_rowptr[node];
    int end = g_rowptr[node + 1];
    for (; e + 8 <= end; e += 8) {
        int2 p[8];
#pragma unroll
        for (int q = 0; q < 8; q++) p[q] = __ldcs(&g_csr[e + q]);
        float4 v_[8];
#pragma unroll
        for (int q = 0; q < 8; q++) v_[q] = ldbf4(h + (size_t)p[q].x * FD + c0);
#pragma unroll
        for (int q = 0; q < 8; q++) {
            float w = __int_as_float(p[q].y);
            ax = fmaf(w, v_[q].x, ax);
            ay = fmaf(w, v_[q].y, ay);
            az = fmaf(w, v_[q].z, az);
            aw = fmaf(w, v_[q].w, aw);
        }
    }
    for (; e + 2 <= end; e += 2) {
        int2 p0 = __ldcs(&g_csr[e]), p1 = __ldcs(&g_csr[e + 1]);
        float4 v0 = ldbf4(h + (size_t)p0.x * FD + c0);
        float4 v1 = ldbf4(h + (size_t)p1.x * FD + c0);
        float w0 = __int_as_float(p0.y), w1 = __int_as_float(p1.y);
        ax += w0 * v0.x + w1 * v1.x;
        ay += w0 * v0.y + w1 * v1.y;
        az += w0 * v0.z + w1 * v1.z;
        aw += w0 * v0.w + w1 * v1.w;
    }
    if (e < end) {
        int2 p = __ldcs(&g_csr[e]);
        float w = __int_as_float(p.y);
        float4 v = ldbf4(h + (size_t)p.x * FD + c0);
        ax += w * v.x; ay += w * v.y; az += w * v.z; aw += w * v.w;
    }

    float4 b4 = *(const float4*)(bias + c0);
    float xx = ax + b4.x, xy = ay + b4.y, xz = az + b4.z, xw = aw + b4.w;

    float s = xx + xy + xz + xw;
#pragma unroll
    for (int o = 16; o > 0; o >>= 1) s += __shfl_xor_sync(0xffffffffu, s, o);
    float mean = s * (1.f / FD);
    float dx = xx - mean, dy = xy - mean, dz = xz - mean, dw = xw - mean;
    float ss = dx * dx + dy * dy + dz * dz + dw * dw;
#pragma unroll
    for (int o = 16; o > 0; o >>= 1) ss += __shfl_xor_sync(0xffffffffu, ss, o);
    float inv = rsqrtf(ss * (1.f / FD) + LN_EPS);

    float4 g4  = *(const float4*)(gamma + c0);
    float4 be4 = *(const float4*)(beta + c0);
    float4 y;
    y.x = fmaxf(dx * inv * g4.x + be4.x, 0.f);
    y.y = fmaxf(dy * inv * g4.y + be4.y, 0.f);
    y.z = fmaxf(dz * inv * g4.z + be4.z, 0.f);
    y.w = fmaxf(dw * inv * g4.w + be4.w, 0.f);
    return y;
}

// ---------------- layer-1 aggregation (writes 128-dim y, fp32) ----------------
__global__ void __launch_bounds__(512) k_agg_ln(const __nv_bfloat16* __restrict__ h,
                                                const float* __restrict__ bias,
                                                const float* __restrict__ gamma,
                                                const float* __restrict__ beta,
                                                float* __restrict__ out) {
    int gw = (blockIdx.x * blockDim.x + threadIdx.x) >> 5;
    if (gw >= NN) return;
    int lane = threadIdx.x & 31;
    float4 y = agg_ln_core(h, bias, gamma, beta, gw, lane);
    *(float4*)(out + (size_t)gw * FD + lane * 4) = y;
}

// ---------------- layer-2 agg fused with projection — persistent (W3 staged once/CTA) ------
__global__ void __launch_bounds__(256) k_agg_ln_proj(const __nv_bfloat16* __restrict__ h,
                                                     const float* __restrict__ bias,
                                                     const float* __restrict__ gamma,
                                                     const float* __restrict__ beta,
                                                     const float* __restrict__ W3,
                                                     float* __restrict__ h3out) {
    __shared__ float Ws[FD * NC];          // 20 KB, staged ONCE per CTA
    __shared__ float rbuf[8][FD];          // 4 KB
    int tid = threadIdx.x;
    for (int i = tid; i < FD * NC; i += 256) Ws[i] = W3[i];
    __syncthreads();

    int lane = tid & 31;
    int wslot = tid >> 5;
    int c1 = 32 + (lane & 7);

    for (int base = blockIdx.x * 8; base < NN; base += AGG3_GRID * 8) {
        int gw = base + wslot;
        if (gw < NN) {
            float4 y = agg_ln_core(h, bias, gamma, beta, gw, lane);

            *(float4*)&rbuf[wslot][lane * 4] = y;
            __syncwarp();

            float acc0 = 0.f, acc1 = 0.f;
#pragma unroll
            for (int k = 0; k < FD; k++) {
                float xk = rbuf[wslot][k];
                acc0 = fmaf(xk, Ws[k * NC + lane], acc0);
                acc1 = fmaf(xk, Ws[k * NC + c1], acc1);
            }
            h3out[(size_t)gw * NC + lane] = acc0;
            if (lane < 8) h3out[(size_t)gw * NC + 32 + lane] = acc1;
            __syncwarp();
        }
    }
}

// ---------------- output aggregation + bias + log_softmax ----------------
__global__ void __launch_bounds__(512) k_agg_out(const float* __restrict__ h3,
                                                 const float* __restrict__ b3,
                                                 float* __restrict__ out) {
    int gw = (blockIdx.x * blockDim.x + threadIdx.x) >> 5;
    if (gw >= NN) return;
    int lane = threadIdx.x & 31;
    int node = gw;
    bool hi = lane < (NC - 32);
    int c1 = 32 + (lane & 7);

    float dn = g_dinv[node];
    float sw = dn * dn;
    float a0 = sw * __ldg(&h3[(size_t)node * NC + lane]);
    float a1 = sw * __ldg(&h3[(size_t)node * NC + c1]);

    int e   = g_rowptr[node];
    int end = g_rowptr[node + 1];
    for (; e + 4 <= end; e += 4) {
        int2 p[4];
#pragma unroll
        for (int q = 0; q < 4; q++) p[q] = __ldcs(&g_csr[e + q]);
        float v0[4], v1[4];
#pragma unroll
        for (int q = 0; q < 4; q++) {
            v0[q] = __ldg(&h3[(size_t)p[q].x * NC + lane]);
            v1[q] = __ldg(&h3[(size_t)p[q].x * NC + c1]);
        }
#pragma unroll
        for (int q = 0; q < 4; q++) {
            float w = __int_as_float(p[q].y);
            a0 = fmaf(w, v0[q], a0);
            a1 = fmaf(w, v1[q], a1);
        }
    }
    for (; e < end; e++) {
        int2 p = __ldcs(&g_csr[e]);
        float w = __int_as_float(p.y);
        a0 = fmaf(w, __ldg(&h3[(size_t)p.x * NC + lane]), a0);
        a1 = fmaf(w, __ldg(&h3[(size_t)p.x * NC + c1]), a1);
    }

    float x0 = a0 + b3[lane];
    float x1 = hi ? (a1 + b3[32 + lane]) : -1e30f;

    float m = fmaxf(x0, x1);
#pragma unroll
    for (int o = 16; o > 0; o >>= 1) m = fmaxf(m, __shfl_xor_sync(0xffffffffu, m, o));
    float se = __expf(x0 - m) + (hi ? __expf(x1 - m) : 0.f);
#pragma unroll
    for (int o = 16; o > 0; o >>= 1) se += __shfl_xor_sync(0xffffffffu, se, o);
    float L = m + __logf(se);

    out[(size_t)node * NC + lane] = x0 - L;
    if (hi) out[(size_t)node * NC + 32 + lane] = x1 - L;
}

// ---------------- launch ----------------
extern "C" void kernel_launch(void* const* d_in, const int* in_sizes, int n_in,
                              void* d_out, int out_size) {
    const float* x    = (const float*)d_in[0];
    const int*   ei   = (const int*)d_in[1];
    const float* W1   = (const float*)d_in[2];
    const float* b1   = (const float*)d_in[3];
    const float* g1   = (const float*)d_in[4];
    const float* be1  = (const float*)d_in[5];
    const float* W2   = (const float*)d_in[6];
    const float* b2   = (const float*)d_in[7];
    const float* g2   = (const float*)d_in[8];
    const float* be2  = (const float*)d_in[9];
    const float* W3   = (const float*)d_in[10];
    const float* b3   = (const float*)d_in[11];
    float* out = (float*)d_out;

    const int4* src4 = (const int4*)ei;
    const int4* dst4 = (const int4*)(ei + NE);

    float *hB, *h3;
    __nv_bfloat16 *hAb, *w1h, *w1l, *w2h, *w2l;
    cudaGetSymbolAddress((void**)&hAb, g_hAb);
    cudaGetSymbolAddress((void**)&hB, g_hB);
    cudaGetSymbolAddress((void**)&h3, g_h3);
    cudaGetSymbolAddress((void**)&w1h, g_W1hi);
    cudaGetSymbolAddress((void**)&w1l, g_W1lo);
    cudaGetSymbolAddress((void**)&w2h, g_W2hi);
    cudaGetSymbolAddress((void**)&w2l, g_W2lo);
    (void)n_in; (void)in_sizes; (void)out_size;

    cudaFuncSetAttribute(k_gemm_tc, cudaFuncAttributeMaxDynamicSharedMemorySize, GM_SMEM);

    int tE4 = (NE / 4 + 255) / 256;
    int gWarp16 = (NN * 32 + 511) / 512;   // 512-thread blocks, warp per node
    int gSetup = (NN + 255) / 256;

    // 10 launches
    k_setup<<<gSetup, 256>>>(W1, W2);
    k_gemm_tc<<<GEMM_GRID, 256, GM_SMEM>>>(x, w1h, w1l, hAb);
    k_hist<<<tE4, 256>>>(dst4);
    k_scanA<<<NSCAN, SCAN_BLK>>>();
    k_scanB<<<1, 128>>>();
    k_scanC<<<NSCAN, SCAN_BLK>>>();
    k_fill<<<tE4, 256>>>(src4, dst4);

    // layer 1 aggregation (bf16 operand, fp32 out)
    k_agg_ln<<<gWarp16, 512>>>(hAb, b1, g1, be1, hB);
    // layer 2 gemm (fp32 in, bf16 out)
    k_gemm_tc<<<GEMM_GRID, 256, GM_SMEM>>>(hB, w2h, w2l, hAb);
    // layer 2 aggregation fused with W3 projection (persistent)
    k_agg_ln_proj<<<AGG3_GRID, 256>>>(hAb, b2, g2, be2, W3, h3);
    // output aggregation + log_softmax
    k_agg_out<<<gWarp16, 512>>>(h3, b3, out);
}

// round 16
// speedup vs baseline: 1.2119x; 1.0381x over previous
#include <cuda_runtime.h>
#include <cuda_bf16.h>
#include <cstdint>

#define NN 100000
#define NE 1600000
#define FD 128
#define NC 40
#define SCAN_BLK 1024
#define NSCAN ((NN + SCAN_BLK - 1) / SCAN_BLK)   // 98
#define LN_EPS 1e-5f
#define NTILES ((NN + 63) / 64)                  // 1563
#define GEMM_GRID 296                            // 2 CTAs/SM * 148 SMs
#define AGG3_GRID 1184                           // persistent fused agg+proj

// ---------------- scratch (static device arrays; no allocation) ----------------
__device__ int   g_count[NN];
__device__ int   g_rowptr[NN + 1];
__device__ int   g_cursor[NN];
__device__ float g_dinv[NN];
__device__ int2  g_csr[NE];            // x = src, y = __float_as_int(w)
__device__ __nv_bfloat16 g_hAb[(size_t)NN * FD];   // gemm output (agg operand)
__device__ __nv_bfloat16 g_hBb[(size_t)NN * FD];   // agg_ln output (gemm2 input)
__device__ float g_h3[(size_t)NN * NC];
__device__ int   g_bsum[NSCAN];
__device__ int   g_boff[NSCAN];
// bf16-split W images, transposed: [n][k] row-major, k contiguous
__device__ __nv_bfloat16 g_W1hi[FD * FD];
__device__ __nv_bfloat16 g_W1lo[FD * FD];
__device__ __nv_bfloat16 g_W2hi[FD * FD];
__device__ __nv_bfloat16 g_W2lo[FD * FD];

// ---------------- helpers ----------------
__device__ __forceinline__ uint32_t smem_u32(const void* p) {
    uint32_t a;
    asm("{ .reg .u64 t; cvta.to.shared.u64 t, %1; cvt.u32.u64 %0, t; }" : "=r"(a) : "l"(p));
    return a;
}
__device__ __forceinline__ float4 ldbf4(const __nv_bfloat16* p) {
    uint2 raw = *(const uint2*)p;
    __nv_bfloat162 a = *reinterpret_cast<__nv_bfloat162*>(&raw.x);
    __nv_bfloat162 b = *reinterpret_cast<__nv_bfloat162*>(&raw.y);
    float2 fa = __bfloat1622float2(a);
    float2 fb = __bfloat1622float2(b);
    return make_float4(fa.x, fa.y, fb.x, fb.y);
}
#define LDSM_X4(r0, r1, r2, r3, addr) \
    asm volatile("ldmatrix.sync.aligned.m8n8.x4.shared.b16 {%0,%1,%2,%3}, [%4];" \
                 : "=r"(r0), "=r"(r1), "=r"(r2), "=r"(r3) : "r"(addr))
#define LDSM_X2(r0, r1, addr) \
    asm volatile("ldmatrix.sync.aligned.m8n8.x2.shared.b16 {%0,%1}, [%2];" \
                 : "=r"(r0), "=r"(r1) : "r"(addr))
#define MMA_BF16(d, a, b) \
    asm volatile("mma.sync.aligned.m16n8k16.row.col.f32.bf16.bf16.f32 " \
                 "{%0,%1,%2,%3}, {%4,%5,%6,%7}, {%8,%9}, {%0,%1,%2,%3};" \
                 : "+f"((d)[0]), "+f"((d)[1]), "+f"((d)[2]), "+f"((d)[3]) \
                 : "r"((a)[0]), "r"((a)[1]), "r"((a)[2]), "r"((a)[3]), \
                   "r"((b)[0]), "r"((b)[1]))

// smem tile geometry: bf16, row stride 136 elems (272B) -> conflict-free ldmatrix
#define TSTRIDE 136
#define ATILE_B (64 * TSTRIDE * 2)    // 17408 bytes (M=64)
#define BTILE_B (128 * TSTRIDE * 2)   // 34816 bytes
#define AHI_B   0
#define ALO_B   (ATILE_B)
#define BHI_B   (2 * ATILE_B)
#define BLO_B   (2 * ATILE_B + BTILE_B)
#define GM_SMEM (2 * ATILE_B + 2 * BTILE_B)   // 104448 bytes -> 2 CTAs/SM
// bf16-input gemm layout: A at 0, W after
#define B2HI_B  (ATILE_B)
#define B2LO_B  (ATILE_B + BTILE_B)
#define GM_SMEM2 (ATILE_B + 2 * BTILE_B)      // 87040 bytes -> 2 CTAs/SM

// ---------------- fused setup: W1/W2 bf16 split + count zeroing ----------------
__global__ void k_setup(const float* __restrict__ W1, const float* __restrict__ W2) {
    int i = blockIdx.x * blockDim.x + threadIdx.x;
    if (i < FD * FD) {
        int k = i >> 7, n = i & 127;
        float v1 = W1[i];
        __nv_bfloat16 h1 = __float2bfloat16_rn(v1);
        g_W1hi[n * FD + k] = h1;
        g_W1lo[n * FD + k] = __float2bfloat16_rn(v1 - __bfloat162float(h1));
        float v2 = W2[i];
        __nv_bfloat16 h2 = __float2bfloat16_rn(v2);
        g_W2hi[n * FD + k] = h2;
        g_W2lo[n * FD + k] = __float2bfloat16_rn(v2 - __bfloat162float(h2));
    }
    if (i < NN) g_count[i] = 0;
}

// ---------------- persistent tensor-core GEMM (fp32 in, bf16-split 3-pass) ----------------
__device__ __forceinline__ void load_A_regs(float4 (&buf)[8], const float* __restrict__ A,
                                            int r0, int tid) {
#pragma unroll
    for (int i = 0; i < 8; i++) {
        int idx = tid + i * 256;
        int row = idx >> 5;
        int c = (idx & 31) * 4;
        int gr = r0 + row;
        buf[i] = (gr < NN) ? *(const float4*)(A + (size_t)gr * FD + c)
                           : make_float4(0.f, 0.f, 0.f, 0.f);
    }
}

__global__ void __launch_bounds__(256, 2) k_gemm_tc(const float* __restrict__ A,
                                                    const __nv_bfloat16* __restrict__ Whi,
                                                    const __nv_bfloat16* __restrict__ Wlo,
                                                    __nv_bfloat16* __restrict__ C) {
    extern __shared__ char smem[];
    uint32_t sb = smem_u32(smem);
    int tid = threadIdx.x;
    int wid = tid >> 5, lane = tid & 31;

    {
        const uint4* sh = (const uint4*)Whi;
        const uint4* sl = (const uint4*)Wlo;
        for (int i = tid; i < 2048; i += 256) {
            int n = i >> 4, kg = (i & 15) * 8;
            *(uint4*)(smem + BHI_B + (n * TSTRIDE + kg) * 2) = sh[i];
            *(uint4*)(smem + BLO_B + (n * TSTRIDE + kg) * 2) = sl[i];
        }
    }

    int warpRow = wid >> 2;
    int warpCol = wid & 3;
    uint32_t aoff = ((warpRow * 32 + (lane & 15)) * TSTRIDE + (lane >> 4) * 8) * 2;
    uint32_t aHiB = sb + AHI_B + aoff;
    uint32_t aLoB = sb + ALO_B + aoff;
    uint32_t boff = ((warpCol * 32 + (lane & 7)) * TSTRIDE + ((lane >> 3) & 1) * 8) * 2;
    uint32_t bHiB = sb + BHI_B + boff;
    uint32_t bLoB = sb + BLO_B + boff;
    int gid = lane >> 2, tg = lane & 3;

    int t = blockIdx.x;
    float4 buf[8];
    if (t < NTILES) load_A_regs(buf, A, t * 64, tid);

    for (; t < NTILES; t += GEMM_GRID) {
        int r0 = t * 64;
        __syncthreads();

#pragma unroll
        for (int i = 0; i < 8; i++) {
            int idx = tid + i * 256;
            int row = idx >> 5;
            int c = (idx & 31) * 4;
            float4 v = buf[i];
            __nv_bfloat16 h0 = __float2bfloat16_rn(v.x), h1 = __float2bfloat16_rn(v.y);
            __nv_bfloat16 h2 = __float2bfloat16_rn(v.z), h3 = __float2bfloat16_rn(v.w);
            __nv_bfloat16 l0 = __float2bfloat16_rn(v.x - __bfloat162float(h0));
            __nv_bfloat16 l1 = __float2bfloat16_rn(v.y - __bfloat162float(h1));
            __nv_bfloat16 l2 = __float2bfloat16_rn(v.z - __bfloat162float(h2));
            __nv_bfloat16 l3 = __float2bfloat16_rn(v.w - __bfloat162float(h3));
            uint32_t hp0 = (uint32_t)__bfloat16_as_ushort(h0) | ((uint32_t)__bfloat16_as_ushort(h1) << 16);
            uint32_t hp1 = (uint32_t)__bfloat16_as_ushort(h2) | ((uint32_t)__bfloat16_as_ushort(h3) << 16);
            uint32_t lp0 = (uint32_t)__bfloat16_as_ushort(l0) | ((uint32_t)__bfloat16_as_ushort(l1) << 16);
            uint32_t lp1 = (uint32_t)__bfloat16_as_ushort(l2) | ((uint32_t)__bfloat16_as_ushort(l3) << 16);
            uint32_t off = (row * TSTRIDE + c) * 2;
            *(uint2*)(smem + AHI_B + off) = make_uint2(hp0, hp1);
            *(uint2*)(smem + ALO_B + off) = make_uint2(lp0, lp1);
        }
        __syncthreads();

        int tn = t + GEMM_GRID;
        if (tn < NTILES) load_A_regs(buf, A, tn * 64, tid);

        float acc[2][4][4];
#pragma unroll
        for (int mi = 0; mi < 2; mi++)
#pragma unroll
            for (int nj = 0; nj < 4; nj++)
#pragma unroll
                for (int q = 0; q < 4; q++) acc[mi][nj][q] = 0.f;

#pragma unroll
        for (int kt = 0; kt < 8; kt++) {
            uint32_t ka = kt * 32;
            uint32_t ah[2][4], al[2][4], bh[4][2], bl[4][2];
#pragma unroll
            for (int mi = 0; mi < 2; mi++) {
                uint32_t d = mi * (16 * TSTRIDE * 2) + ka;
                LDSM_X4(ah[mi][0], ah[mi][1], ah[mi][2], ah[mi][3], aHiB + d);
                LDSM_X4(al[mi][0], al[mi][1], al[mi][2], al[mi][3], aLoB + d);
            }
#pragma unroll
            for (int nj = 0; nj < 4; nj++) {
                uint32_t d = nj * (8 * TSTRIDE * 2) + ka;
                LDSM_X2(bh[nj][0], bh[nj][1], bHiB + d);
                LDSM_X2(bl[nj][0], bl[nj][1], bLoB + d);
            }
#pragma unroll
            for (int mi = 0; mi < 2; mi++)
#pragma unroll
                for (int nj = 0; nj < 4; nj++) {
                    MMA_BF16(acc[mi][nj], ah[mi], bh[nj]);
                    MMA_BF16(acc[mi][nj], ah[mi], bl[nj]);
                    MMA_BF16(acc[mi][nj], al[mi], bh[nj]);
                }
        }

#pragma unroll
        for (int mi = 0; mi < 2; mi++) {
            int r = r0 + warpRow * 32 + mi * 16 + gid;
#pragma unroll
            for (int nj = 0; nj < 4; nj++) {
                int cb = warpCol * 32 + nj * 8 + tg * 2;
                if (r < NN) {
                    __nv_bfloat162 v;
                    v.x = __float2bfloat16_rn(acc[mi][nj][0]);
                    v.y = __float2bfloat16_rn(acc[mi][nj][1]);
                    *(__nv_bfloat162*)(C + (size_t)r * FD + cb) = v;
                }
                if (r + 8 < NN) {
                    __nv_bfloat162 v;
                    v.x = __float2bfloat16_rn(acc[mi][nj][2]);
                    v.y = __float2bfloat16_rn(acc[mi][nj][3]);
                    *(__nv_bfloat162*)(C + (size_t)(r + 8) * FD + cb) = v;
                }
            }
        }
    }
}

// ---------------- persistent GEMM, bf16 input (2-pass: Ahi*Whi + Ahi*Wlo) ----------------
__device__ __forceinline__ void load_Ab_regs(uint4 (&buf)[4], const __nv_bfloat16* __restrict__ A,
                                             int r0, int tid) {
#pragma unroll
    for (int i = 0; i < 4; i++) {
        int idx = tid + i * 256;            // 1024 uint4 total
        int row = idx >> 4;
        int c8 = (idx & 15) * 8;
        int gr = r0 + row;
        buf[i] = (gr < NN) ? *(const uint4*)(A + (size_t)gr * FD + c8)
                           : make_uint4(0u, 0u, 0u, 0u);
    }
}

__global__ void __launch_bounds__(256, 2) k_gemm_tc_b(const __nv_bfloat16* __restrict__ A,
                                                      const __nv_bfloat16* __restrict__ Whi,
                                                      const __nv_bfloat16* __restrict__ Wlo,
                                                      __nv_bfloat16* __restrict__ C) {
    extern __shared__ char smem[];
    uint32_t sb = smem_u32(smem);
    int tid = threadIdx.x;
    int wid = tid >> 5, lane = tid & 31;

    {
        const uint4* sh = (const uint4*)Whi;
        const uint4* sl = (const uint4*)Wlo;
        for (int i = tid; i < 2048; i += 256) {
            int n = i >> 4, kg = (i & 15) * 8;
            *(uint4*)(smem + B2HI_B + (n * TSTRIDE + kg) * 2) = sh[i];
            *(uint4*)(smem + B2LO_B + (n * TSTRIDE + kg) * 2) = sl[i];
        }
    }

    int warpRow = wid >> 2;
    int warpCol = wid & 3;
    uint32_t aoff = ((warpRow * 32 + (lane & 15)) * TSTRIDE + (lane >> 4) * 8) * 2;
    uint32_t aB = sb + aoff;   // A at smem offset 0
    uint32_t boff = ((warpCol * 32 + (lane & 7)) * TSTRIDE + ((lane >> 3) & 1) * 8) * 2;
    uint32_t bHiB = sb + B2HI_B + boff;
    uint32_t bLoB = sb + B2LO_B + boff;
    int gid = lane >> 2, tg = lane & 3;

    int t = blockIdx.x;
    uint4 buf[4];
    if (t < NTILES) load_Ab_regs(buf, A, t * 64, tid);

    for (; t < NTILES; t += GEMM_GRID) {
        int r0 = t * 64;
        __syncthreads();

#pragma unroll
        for (int i = 0; i < 4; i++) {
            int idx = tid + i * 256;
            int row = idx >> 4;
            int c8 = (idx & 15) * 8;
            *(uint4*)(smem + (row * TSTRIDE + c8) * 2) = buf[i];
        }
        __syncthreads();

        int tn = t + GEMM_GRID;
        if (tn < NTILES) load_Ab_regs(buf, A, tn * 64, tid);

        float acc[2][4][4];
#pragma unroll
        for (int mi = 0; mi < 2; mi++)
#pragma unroll
            for (int nj = 0; nj < 4; nj++)
#pragma unroll
                for (int q = 0; q < 4; q++) acc[mi][nj][q] = 0.f;

#pragma unroll
        for (int kt = 0; kt < 8; kt++) {
            uint32_t ka = kt * 32;
            uint32_t ah[2][4], bh[4][2], bl[4][2];
#pragma unroll
            for (int mi = 0; mi < 2; mi++) {
                uint32_t d = mi * (16 * TSTRIDE * 2) + ka;
                LDSM_X4(ah[mi][0], ah[mi][1], ah[mi][2], ah[mi][3], aB + d);
            }
#pragma unroll
            for (int nj = 0; nj < 4; nj++) {
                uint32_t d = nj * (8 * TSTRIDE * 2) + ka;
                LDSM_X2(bh[nj][0], bh[nj][1], bHiB + d);
                LDSM_X2(bl[nj][0], bl[nj][1], bLoB + d);
            }
#pragma unroll
            for (int mi = 0; mi < 2; mi++)
#pragma unroll
                for (int nj = 0; nj < 4; nj++) {
                    MMA_BF16(acc[mi][nj], ah[mi], bh[nj]);
                    MMA_BF16(acc[mi][nj], ah[mi], bl[nj]);
                }
        }

#pragma unroll
        for (int mi = 0; mi < 2; mi++) {
            int r = r0 + warpRow * 32 + mi * 16 + gid;
#pragma unroll
            for (int nj = 0; nj < 4; nj++) {
                int cb = warpCol * 32 + nj * 8 + tg * 2;
                if (r < NN) {
                    __nv_bfloat162 v;
                    v.x = __float2bfloat16_rn(acc[mi][nj][0]);
                    v.y = __float2bfloat16_rn(acc[mi][nj][1]);
                    *(__nv_bfloat162*)(C + (size_t)r * FD + cb) = v;
                }
                if (r + 8 < NN) {
                    __nv_bfloat162 v;
                    v.x = __float2bfloat16_rn(acc[mi][nj][2]);
                    v.y = __float2bfloat16_rn(acc[mi][nj][3]);
                    *(__nv_bfloat162*)(C + (size_t)(r + 8) * FD + cb) = v;
                }
            }
        }
    }
}

// ---------------- CSR build ----------------
__global__ void k_hist(const int4* __restrict__ dst4) {
    int e4 = blockIdx.x * blockDim.x + threadIdx.x;
    if (e4 >= NE / 4) return;
    int4 d = dst4[e4];
    atomicAdd(&g_count[d.x], 1);
    atomicAdd(&g_count[d.y], 1);
    atomicAdd(&g_count[d.z], 1);
    atomicAdd(&g_count[d.w], 1);
}

__global__ void k_scanA() {
    __shared__ int sh[SCAN_BLK];
    int i = blockIdx.x * SCAN_BLK + threadIdx.x;
    int v = (i < NN) ? g_count[i] : 0;
    if (i < NN) g_dinv[i] = rsqrtf((float)(v + 1));   // +1 self-loop
    sh[threadIdx.x] = v;
    __syncthreads();
    for (int off = SCAN_BLK / 2; off > 0; off >>= 1) {
        if (threadIdx.x < off) sh[threadIdx.x] += sh[threadIdx.x + off];
        __syncthreads();
    }
    if (threadIdx.x == 0) g_bsum[blockIdx.x] = sh[0];
}

__global__ void k_scanB() {
    __shared__ int sh[NSCAN];
    if (threadIdx.x < NSCAN) sh[threadIdx.x] = g_bsum[threadIdx.x];
    __syncthreads();
    if (threadIdx.x == 0) {
        int run = 0;
        for (int b = 0; b < NSCAN; b++) { int t = sh[b]; sh[b] = run; run += t; }
        g_rowptr[NN] = run;
    }
    __syncthreads();
    if (threadIdx.x < NSCAN) g_boff[threadIdx.x] = sh[threadIdx.x];
}

__global__ void k_scanC() {
    __shared__ int sh[SCAN_BLK];
    int i = blockIdx.x * SCAN_BLK + threadIdx.x;
    int v = (i < NN) ? g_count[i] : 0;
    sh[threadIdx.x] = v;
    __syncthreads();
    for (int off = 1; off < SCAN_BLK; off <<= 1) {
        int t = (threadIdx.x >= off) ? sh[threadIdx.x - off] : 0;
        __syncthreads();
        sh[threadIdx.x] += t;
        __syncthreads();
    }
    if (i < NN) {
        int excl = sh[threadIdx.x] - v + g_boff[blockIdx.x];
        g_rowptr[i] = excl;
        g_cursor[i] = excl;
    }
}

__global__ void k_fill(const int4* __restrict__ src4, const int4* __restrict__ dst4) {
    int e4 = blockIdx.x * blockDim.x + threadIdx.x;
    if (e4 >= NE / 4) return;
    int4 s = src4[e4];
    int4 d = dst4[e4];
    int ss[4] = {s.x, s.y, s.z, s.w};
    int dd[4] = {d.x, d.y, d.z, d.w};
#pragma unroll
    for (int q = 0; q < 4; q++) {
        int idx = atomicAdd(&g_cursor[dd[q]], 1);
        g_csr[idx] = make_int2(ss[q], __float_as_int(g_dinv[ss[q]] * g_dinv[dd[q]]));
    }
}

// ---------------- agg + bias + LN + ReLU core over bf16 h (returns y in float4) -------------
__device__ __forceinline__ float4 agg_ln_core(const __nv_bfloat16* __restrict__ h,
                                              const float* __restrict__ bias,
                                              const float* __restrict__ gamma,
                                              const float* __restrict__ beta,
                                              int node, int lane) {
    int c0 = lane * 4;
    float dn = g_dinv[node];
    float sw = dn * dn;
    float4 hv = ldbf4(h + (size_t)node * FD + c0);
    float ax = sw * hv.x, ay = sw * hv.y, az = sw * hv.z, aw = sw * hv.w;

    int e   = g_rowptr[node];
    int end = g_rowptr[node + 1];
    for (; e + 8 <= end; e += 8) {
        int2 p[8];
#pragma unroll
        for (int q = 0; q < 8; q++) p[q] = __ldcs(&g_csr[e + q]);
        float4 v_[8];
#pragma unroll
        for (int q = 0; q < 8; q++) v_[q] = ldbf4(h + (size_t)p[q].x * FD + c0);
#pragma unroll
        for (int q = 0; q < 8; q++) {
            float w = __int_as_float(p[q].y);
            ax = fmaf(w, v_[q].x, ax);
            ay = fmaf(w, v_[q].y, ay);
            az = fmaf(w, v_[q].z, az);
            aw = fmaf(w, v_[q].w, aw);
        }
    }
    for (; e + 2 <= end; e += 2) {
        int2 p0 = __ldcs(&g_csr[e]), p1 = __ldcs(&g_csr[e + 1]);
        float4 v0 = ldbf4(h + (size_t)p0.x * FD + c0);
        float4 v1 = ldbf4(h + (size_t)p1.x * FD + c0);
        float w0 = __int_as_float(p0.y), w1 = __int_as_float(p1.y);
        ax += w0 * v0.x + w1 * v1.x;
        ay += w0 * v0.y + w1 * v1.y;
        az += w0 * v0.z + w1 * v1.z;
        aw += w0 * v0.w + w1 * v1.w;
    }
    if (e < end) {
        int2 p = __ldcs(&g_csr[e]);
        float w = __int_as_float(p.y);
        float4 v = ldbf4(h + (size_t)p.x * FD + c0);
        ax += w * v.x; ay += w * v.y; az += w * v.z; aw += w * v.w;
    }

    float4 b4 = *(const float4*)(bias + c0);
    float xx = ax + b4.x, xy = ay + b4.y, xz = az + b4.z, xw = aw + b4.w;

    float s = xx + xy + xz + xw;
#pragma unroll
    for (int o = 16; o > 0; o >>= 1) s += __shfl_xor_sync(0xffffffffu, s, o);
    float mean = s * (1.f / FD);
    float dx = xx - mean, dy = xy - mean, dz = xz - mean, dw = xw - mean;
    float ss = dx * dx + dy * dy + dz * dz + dw * dw;
#pragma unroll
    for (int o = 16; o > 0; o >>= 1) ss += __shfl_xor_sync(0xffffffffu, ss, o);
    float inv = rsqrtf(ss * (1.f / FD) + LN_EPS);

    float4 g4  = *(const float4*)(gamma + c0);
    float4 be4 = *(const float4*)(beta + c0);
    float4 y;
    y.x = fmaxf(dx * inv * g4.x + be4.x, 0.f);
    y.y = fmaxf(dy * inv * g4.y + be4.y, 0.f);
    y.z = fmaxf(dz * inv * g4.z + be4.z, 0.f);
    y.w = fmaxf(dw * inv * g4.w + be4.w, 0.f);
    return y;
}

// ---------------- layer-1 aggregation (writes 128-dim y, bf16) ----------------
__global__ void __launch_bounds__(512) k_agg_ln(const __nv_bfloat16* __restrict__ h,
                                                const float* __restrict__ bias,
                                                const float* __restrict__ gamma,
                                                const float* __restrict__ beta,
                                                __nv_bfloat16* __restrict__ out) {
    int gw = (blockIdx.x * blockDim.x + threadIdx.x) >> 5;
    if (gw >= NN) return;
    int lane = threadIdx.x & 31;
    float4 y = agg_ln_core(h, bias, gamma, beta, gw, lane);
    __nv_bfloat162 p0 = __floats2bfloat162_rn(y.x, y.y);
    __nv_bfloat162 p1 = __floats2bfloat162_rn(y.z, y.w);
    uint2 packed;
    packed.x = *reinterpret_cast<uint32_t*>(&p0);
    packed.y = *reinterpret_cast<uint32_t*>(&p1);
    *(uint2*)(out + (size_t)gw * FD + lane * 4) = packed;
}

// ---------------- layer-2 agg fused with projection — persistent (W3 staged once/CTA) ------
__global__ void __launch_bounds__(256) k_agg_ln_proj(const __nv_bfloat16* __restrict__ h,
                                                     const float* __restrict__ bias,
                                                     const float* __restrict__ gamma,
                                                     const float* __restrict__ beta,
                                                     const float* __restrict__ W3,
                                                     float* __restrict__ h3out) {
    __shared__ float Ws[FD * NC];          // 20 KB, staged ONCE per CTA
    __shared__ float rbuf[8][FD];          // 4 KB
    int tid = threadIdx.x;
    for (int i = tid; i < FD * NC; i += 256) Ws[i] = W3[i];
    __syncthreads();

    int lane = tid & 31;
    int wslot = tid >> 5;
    int c1 = 32 + (lane & 7);

    for (int base = blockIdx.x * 8; base < NN; base += AGG3_GRID * 8) {
        int gw = base + wslot;
        if (gw < NN) {
            float4 y = agg_ln_core(h, bias, gamma, beta, gw, lane);

            *(float4*)&rbuf[wslot][lane * 4] = y;
            __syncwarp();

            float acc0 = 0.f, acc1 = 0.f;
#pragma unroll
            for (int k = 0; k < FD; k++) {
                float xk = rbuf[wslot][k];
                acc0 = fmaf(xk, Ws[k * NC + lane], acc0);
                acc1 = fmaf(xk, Ws[k * NC + c1], acc1);
            }
            h3out[(size_t)gw * NC + lane] = acc0;
            if (lane < 8) h3out[(size_t)gw * NC + 32 + lane] = acc1;
            __syncwarp();
        }
    }
}

// ---------------- output aggregation + bias + log_softmax ----------------
__global__ void __launch_bounds__(512) k_agg_out(const float* __restrict__ h3,
                                                 const float* __restrict__ b3,
                                                 float* __restrict__ out) {
    int gw = (blockIdx.x * blockDim.x + threadIdx.x) >> 5;
    if (gw >= NN) return;
    int lane = threadIdx.x & 31;
    int node = gw;
    bool hi = lane < (NC - 32);
    int c1 = 32 + (lane & 7);

    float dn = g_dinv[node];
    float sw = dn * dn;
    float a0 = sw * __ldg(&h3[(size_t)node * NC + lane]);
    float a1 = sw * __ldg(&h3[(size_t)node * NC + c1]);

    int e   = g_rowptr[node];
    int end = g_rowptr[node + 1];
    for (; e + 4 <= end; e += 4) {
        int2 p[4];
#pragma unroll
        for (int q = 0; q < 4; q++) p[q] = __ldcs(&g_csr[e + q]);
        float v0[4], v1[4];
#pragma unroll
        for (int q = 0; q < 4; q++) {
            v0[q] = __ldg(&h3[(size_t)p[q].x * NC + lane]);
            v1[q] = __ldg(&h3[(size_t)p[q].x * NC + c1]);
        }
#pragma unroll
        for (int q = 0; q < 4; q++) {
            float w = __int_as_float(p[q].y);
            a0 = fmaf(w, v0[q], a0);
            a1 = fmaf(w, v1[q], a1);
        }
    }
    for (; e < end; e++) {
        int2 p = __ldcs(&g_csr[e]);
        float w = __int_as_float(p.y);
        a0 = fmaf(w, __ldg(&h3[(size_t)p.x * NC + lane]), a0);
        a1 = fmaf(w, __ldg(&h3[(size_t)p.x * NC + c1]), a1);
    }

    float x0 = a0 + b3[lane];
    float x1 = hi ? (a1 + b3[32 + lane]) : -1e30f;

    float m = fmaxf(x0, x1);
#pragma unroll
    for (int o = 16; o > 0; o >>= 1) m = fmaxf(m, __shfl_xor_sync(0xffffffffu, m, o));
    float se = __expf(x0 - m) + (hi ? __expf(x1 - m) : 0.f);
#pragma unroll
    for (int o = 16; o > 0; o >>= 1) se += __shfl_xor_sync(0xffffffffu, se, o);
    float L = m + __logf(se);

    out[(size_t)node * NC + lane] = x0 - L;
    if (hi) out[(size_t)node * NC + 32 + lane] = x1 - L;
}

// ---------------- launch ----------------
extern "C" void kernel_launch(void* const* d_in, const int* in_sizes, int n_in,
                              void* d_out, int out_size) {
    const float* x    = (const float*)d_in[0];
    const int*   ei   = (const int*)d_in[1];
    const float* W1   = (const float*)d_in[2];
    const float* b1   = (const float*)d_in[3];
    const float* g1   = (const float*)d_in[4];
    const float* be1  = (const float*)d_in[5];
    const float* W2   = (const float*)d_in[6];
    const float* b2   = (const float*)d_in[7];
    const float* g2   = (const float*)d_in[8];
    const float* be2  = (const float*)d_in[9];
    const float* W3   = (const float*)d_in[10];
    const float* b3   = (const float*)d_in[11];
    float* out = (float*)d_out;

    const int4* src4 = (const int4*)ei;
    const int4* dst4 = (const int4*)(ei + NE);

    float *h3;
    __nv_bfloat16 *hAb, *hBb, *w1h, *w1l, *w2h, *w2l;
    cudaGetSymbolAddress((void**)&hAb, g_hAb);
    cudaGetSymbolAddress((void**)&hBb, g_hBb);
    cudaGetSymbolAddress((void**)&h3, g_h3);
    cudaGetSymbolAddress((void**)&w1h, g_W1hi);
    cudaGetSymbolAddress((void**)&w1l, g_W1lo);
    cudaGetSymbolAddress((void**)&w2h, g_W2hi);
    cudaGetSymbolAddress((void**)&w2l, g_W2lo);
    (void)n_in; (void)in_sizes; (void)out_size;

    cudaFuncSetAttribute(k_gemm_tc, cudaFuncAttributeMaxDynamicSharedMemorySize, GM_SMEM);
    cudaFuncSetAttribute(k_gemm_tc_b, cudaFuncAttributeMaxDynamicSharedMemorySize, GM_SMEM2);

    int tE4 = (NE / 4 + 255) / 256;
    int gWarp16 = (NN * 32 + 511) / 512;
    int gSetup = (NN + 255) / 256;

    // 10 launches
    k_setup<<<gSetup, 256>>>(W1, W2);
    k_gemm_tc<<<GEMM_GRID, 256, GM_SMEM>>>(x, w1h, w1l, hAb);
    k_hist<<<tE4, 256>>>(dst4);
    k_scanA<<<NSCAN, SCAN_BLK>>>();
    k_scanB<<<1, 128>>>();
    k_scanC<<<NSCAN, SCAN_BLK>>>();
    k_fill<<<tE4, 256>>>(src4, dst4);

    // layer 1 aggregation (bf16 in, bf16 out)
    k_agg_ln<<<gWarp16, 512>>>(hAb, b1, g1, be1, hBb);
    // layer 2 gemm: bf16 input, 2-pass
    k_gemm_tc_b<<<GEMM_GRID, 256, GM_SMEM2>>>(hBb, w2h, w2l, hAb);
    // layer 2 aggregation fused with W3 projection (persistent)
    k_agg_ln_proj<<<AGG3_GRID, 256>>>(hAb, b2, g2, be2, W3, h3);
    // output aggregation + log_softmax
    k_agg_out<<<gWarp16, 512>>>(h3, b3, out);
}

// round 17
// speedup vs baseline: 1.2559x; 1.0363x over previous
#include <cuda_runtime.h>
#include <cuda_bf16.h>
#include <cstdint>

#define NN 100000
#define NE 1600000
#define FD 128
#define NC 40
#define SCAN_BLK 1024
#define NSCAN ((NN + SCAN_BLK - 1) / SCAN_BLK)   // 98
#define LN_EPS 1e-5f
#define NTILES ((NN + 63) / 64)                  // 1563
#define GEMM_GRID 296                            // 2 CTAs/SM * 148 SMs
#define AGG3_GRID 1184                           // persistent fused agg+proj

// ---------------- scratch (static device arrays; no allocation) ----------------
__device__ int   g_count[NN];
__device__ int   g_rowptr[NN + 1];
__device__ int   g_cursor[NN];
__device__ float g_dinv[NN];
__device__ int   g_csrs[NE];           // src index only (weights factored out)
__device__ __nv_bfloat16 g_hAb[(size_t)NN * FD];   // scaled gemm output hs = dinv*h
__device__ __nv_bfloat16 g_hBb[(size_t)NN * FD];   // agg_ln output y (unscaled)
__device__ float g_h3[(size_t)NN * NC];            // scaled projection output
__device__ int   g_bsum[NSCAN];
__device__ int   g_boff[NSCAN];
// bf16-split W images, transposed: [n][k] row-major, k contiguous
__device__ __nv_bfloat16 g_W1hi[FD * FD];
__device__ __nv_bfloat16 g_W1lo[FD * FD];
__device__ __nv_bfloat16 g_W2hi[FD * FD];
__device__ __nv_bfloat16 g_W2lo[FD * FD];

// ---------------- helpers ----------------
__device__ __forceinline__ uint32_t smem_u32(const void* p) {
    uint32_t a;
    asm("{ .reg .u64 t; cvta.to.shared.u64 t, %1; cvt.u32.u64 %0, t; }" : "=r"(a) : "l"(p));
    return a;
}
__device__ __forceinline__ float4 ldbf4(const __nv_bfloat16* p) {
    uint2 raw = *(const uint2*)p;
    __nv_bfloat162 a = *reinterpret_cast<__nv_bfloat162*>(&raw.x);
    __nv_bfloat162 b = *reinterpret_cast<__nv_bfloat162*>(&raw.y);
    float2 fa = __bfloat1622float2(a);
    float2 fb = __bfloat1622float2(b);
    return make_float4(fa.x, fa.y, fb.x, fb.y);
}
#define LDSM_X4(r0, r1, r2, r3, addr) \
    asm volatile("ldmatrix.sync.aligned.m8n8.x4.shared.b16 {%0,%1,%2,%3}, [%4];" \
                 : "=r"(r0), "=r"(r1), "=r"(r2), "=r"(r3) : "r"(addr))
#define LDSM_X2(r0, r1, addr) \
    asm volatile("ldmatrix.sync.aligned.m8n8.x2.shared.b16 {%0,%1}, [%2];" \
                 : "=r"(r0), "=r"(r1) : "r"(addr))
#define MMA_BF16(d, a, b) \
    asm volatile("mma.sync.aligned.m16n8k16.row.col.f32.bf16.bf16.f32 " \
                 "{%0,%1,%2,%3}, {%4,%5,%6,%7}, {%8,%9}, {%0,%1,%2,%3};" \
                 : "+f"((d)[0]), "+f"((d)[1]), "+f"((d)[2]), "+f"((d)[3]) \
                 : "r"((a)[0]), "r"((a)[1]), "r"((a)[2]), "r"((a)[3]), \
                   "r"((b)[0]), "r"((b)[1]))

// smem tile geometry: bf16, row stride 136 elems (272B) -> conflict-free ldmatrix
#define TSTRIDE 136
#define ATILE_B (64 * TSTRIDE * 2)    // 17408 bytes (M=64)
#define BTILE_B (128 * TSTRIDE * 2)   // 34816 bytes
#define AHI_B   0
#define ALO_B   (ATILE_B)
#define BHI_B   (2 * ATILE_B)
#define BLO_B   (2 * ATILE_B + BTILE_B)
#define GM_SMEM (2 * ATILE_B + 2 * BTILE_B)   // 104448 bytes -> 2 CTAs/SM
// bf16-input gemm layout: A at 0, W after
#define B2HI_B  (ATILE_B)
#define B2LO_B  (ATILE_B + BTILE_B)
#define GM_SMEM2 (ATILE_B + 2 * BTILE_B)      // 87040 bytes -> 2 CTAs/SM

// ---------------- fused setup: W1/W2 bf16 split + count zeroing ----------------
__global__ void k_setup(const float* __restrict__ W1, const float* __restrict__ W2) {
    int i = blockIdx.x * blockDim.x + threadIdx.x;
    if (i < FD * FD) {
        int k = i >> 7, n = i & 127;
        float v1 = W1[i];
        __nv_bfloat16 h1 = __float2bfloat16_rn(v1);
        g_W1hi[n * FD + k] = h1;
        g_W1lo[n * FD + k] = __float2bfloat16_rn(v1 - __bfloat162float(h1));
        float v2 = W2[i];
        __nv_bfloat16 h2 = __float2bfloat16_rn(v2);
        g_W2hi[n * FD + k] = h2;
        g_W2lo[n * FD + k] = __float2bfloat16_rn(v2 - __bfloat162float(h2));
    }
    if (i < NN) g_count[i] = 0;
}

// ---------------- persistent tensor-core GEMM (fp32 in, 3-pass, dinv-scaled epilogue) -------
__device__ __forceinline__ void load_A_regs(float4 (&buf)[8], const float* __restrict__ A,
                                            int r0, int tid) {
#pragma unroll
    for (int i = 0; i < 8; i++) {
        int idx = tid + i * 256;
        int row = idx >> 5;
        int c = (idx & 31) * 4;
        int gr = r0 + row;
        buf[i] = (gr < NN) ? *(const float4*)(A + (size_t)gr * FD + c)
                           : make_float4(0.f, 0.f, 0.f, 0.f);
    }
}

__global__ void __launch_bounds__(256, 2) k_gemm_tc(const float* __restrict__ A,
                                                    const __nv_bfloat16* __restrict__ Whi,
                                                    const __nv_bfloat16* __restrict__ Wlo,
                                                    __nv_bfloat16* __restrict__ C) {
    extern __shared__ char smem[];
    uint32_t sb = smem_u32(smem);
    int tid = threadIdx.x;
    int wid = tid >> 5, lane = tid & 31;

    {
        const uint4* sh = (const uint4*)Whi;
        const uint4* sl = (const uint4*)Wlo;
        for (int i = tid; i < 2048; i += 256) {
            int n = i >> 4, kg = (i & 15) * 8;
            *(uint4*)(smem + BHI_B + (n * TSTRIDE + kg) * 2) = sh[i];
            *(uint4*)(smem + BLO_B + (n * TSTRIDE + kg) * 2) = sl[i];
        }
    }

    int warpRow = wid >> 2;
    int warpCol = wid & 3;
    uint32_t aoff = ((warpRow * 32 + (lane & 15)) * TSTRIDE + (lane >> 4) * 8) * 2;
    uint32_t aHiB = sb + AHI_B + aoff;
    uint32_t aLoB = sb + ALO_B + aoff;
    uint32_t boff = ((warpCol * 32 + (lane & 7)) * TSTRIDE + ((lane >> 3) & 1) * 8) * 2;
    uint32_t bHiB = sb + BHI_B + boff;
    uint32_t bLoB = sb + BLO_B + boff;
    int gid = lane >> 2, tg = lane & 3;

    int t = blockIdx.x;
    float4 buf[8];
    if (t < NTILES) load_A_regs(buf, A, t * 64, tid);

    for (; t < NTILES; t += GEMM_GRID) {
        int r0 = t * 64;
        __syncthreads();

#pragma unroll
        for (int i = 0; i < 8; i++) {
            int idx = tid + i * 256;
            int row = idx >> 5;
            int c = (idx & 31) * 4;
            float4 v = buf[i];
            __nv_bfloat16 h0 = __float2bfloat16_rn(v.x), h1 = __float2bfloat16_rn(v.y);
            __nv_bfloat16 h2 = __float2bfloat16_rn(v.z), h3 = __float2bfloat16_rn(v.w);
            __nv_bfloat16 l0 = __float2bfloat16_rn(v.x - __bfloat162float(h0));
            __nv_bfloat16 l1 = __float2bfloat16_rn(v.y - __bfloat162float(h1));
            __nv_bfloat16 l2 = __float2bfloat16_rn(v.z - __bfloat162float(h2));
            __nv_bfloat16 l3 = __float2bfloat16_rn(v.w - __bfloat162float(h3));
            uint32_t hp0 = (uint32_t)__bfloat16_as_ushort(h0) | ((uint32_t)__bfloat16_as_ushort(h1) << 16);
            uint32_t hp1 = (uint32_t)__bfloat16_as_ushort(h2) | ((uint32_t)__bfloat16_as_ushort(h3) << 16);
            uint32_t lp0 = (uint32_t)__bfloat16_as_ushort(l0) | ((uint32_t)__bfloat16_as_ushort(l1) << 16);
            uint32_t lp1 = (uint32_t)__bfloat16_as_ushort(l2) | ((uint32_t)__bfloat16_as_ushort(l3) << 16);
            uint32_t off = (row * TSTRIDE + c) * 2;
            *(uint2*)(smem + AHI_B + off) = make_uint2(hp0, hp1);
            *(uint2*)(smem + ALO_B + off) = make_uint2(lp0, lp1);
        }
        __syncthreads();

        int tn = t + GEMM_GRID;
        if (tn < NTILES) load_A_regs(buf, A, tn * 64, tid);

        float acc[2][4][4];
#pragma unroll
        for (int mi = 0; mi < 2; mi++)
#pragma unroll
            for (int nj = 0; nj < 4; nj++)
#pragma unroll
                for (int q = 0; q < 4; q++) acc[mi][nj][q] = 0.f;

#pragma unroll
        for (int kt = 0; kt < 8; kt++) {
            uint32_t ka = kt * 32;
            uint32_t ah[2][4], al[2][4], bh[4][2], bl[4][2];
#pragma unroll
            for (int mi = 0; mi < 2; mi++) {
                uint32_t d = mi * (16 * TSTRIDE * 2) + ka;
                LDSM_X4(ah[mi][0], ah[mi][1], ah[mi][2], ah[mi][3], aHiB + d);
                LDSM_X4(al[mi][0], al[mi][1], al[mi][2], al[mi][3], aLoB + d);
            }
#pragma unroll
            for (int nj = 0; nj < 4; nj++) {
                uint32_t d = nj * (8 * TSTRIDE * 2) + ka;
                LDSM_X2(bh[nj][0], bh[nj][1], bHiB + d);
                LDSM_X2(bl[nj][0], bl[nj][1], bLoB + d);
            }
#pragma unroll
            for (int mi = 0; mi < 2; mi++)
#pragma unroll
                for (int nj = 0; nj < 4; nj++) {
                    MMA_BF16(acc[mi][nj], ah[mi], bh[nj]);
                    MMA_BF16(acc[mi][nj], ah[mi], bl[nj]);
                    MMA_BF16(acc[mi][nj], al[mi], bh[nj]);
                }
        }

#pragma unroll
        for (int mi = 0; mi < 2; mi++) {
            int r = r0 + warpRow * 32 + mi * 16 + gid;
            float dA = (r < NN) ? g_dinv[r] : 0.f;
            float dB = (r + 8 < NN) ? g_dinv[r + 8] : 0.f;
#pragma unroll
            for (int nj = 0; nj < 4; nj++) {
                int cb = warpCol * 32 + nj * 8 + tg * 2;
                if (r < NN) {
                    __nv_bfloat162 v;
                    v.x = __float2bfloat16_rn(dA * acc[mi][nj][0]);
                    v.y = __float2bfloat16_rn(dA * acc[mi][nj][1]);
                    *(__nv_bfloat162*)(C + (size_t)r * FD + cb) = v;
                }
                if (r + 8 < NN) {
                    __nv_bfloat162 v;
                    v.x = __float2bfloat16_rn(dB * acc[mi][nj][2]);
                    v.y = __float2bfloat16_rn(dB * acc[mi][nj][3]);
                    *(__nv_bfloat162*)(C + (size_t)(r + 8) * FD + cb) = v;
                }
            }
        }
    }
}

// ---------------- persistent GEMM, bf16 input (2-pass, dinv-scaled epilogue) ----------------
__device__ __forceinline__ void load_Ab_regs(uint4 (&buf)[4], const __nv_bfloat16* __restrict__ A,
                                             int r0, int tid) {
#pragma unroll
    for (int i = 0; i < 4; i++) {
        int idx = tid + i * 256;
        int row = idx >> 4;
        int c8 = (idx & 15) * 8;
        int gr = r0 + row;
        buf[i] = (gr < NN) ? *(const uint4*)(A + (size_t)gr * FD + c8)
                           : make_uint4(0u, 0u, 0u, 0u);
    }
}

__global__ void __launch_bounds__(256, 2) k_gemm_tc_b(const __nv_bfloat16* __restrict__ A,
                                                      const __nv_bfloat16* __restrict__ Whi,
                                                      const __nv_bfloat16* __restrict__ Wlo,
                                                      __nv_bfloat16* __restrict__ C) {
    extern __shared__ char smem[];
    uint32_t sb = smem_u32(smem);
    int tid = threadIdx.x;
    int wid = tid >> 5, lane = tid & 31;

    {
        const uint4* sh = (const uint4*)Whi;
        const uint4* sl = (const uint4*)Wlo;
        for (int i = tid; i < 2048; i += 256) {
            int n = i >> 4, kg = (i & 15) * 8;
            *(uint4*)(smem + B2HI_B + (n * TSTRIDE + kg) * 2) = sh[i];
            *(uint4*)(smem + B2LO_B + (n * TSTRIDE + kg) * 2) = sl[i];
        }
    }

    int warpRow = wid >> 2;
    int warpCol = wid & 3;
    uint32_t aoff = ((warpRow * 32 + (lane & 15)) * TSTRIDE + (lane >> 4) * 8) * 2;
    uint32_t aB = sb + aoff;
    uint32_t boff = ((warpCol * 32 + (lane & 7)) * TSTRIDE + ((lane >> 3) & 1) * 8) * 2;
    uint32_t bHiB = sb + B2HI_B + boff;
    uint32_t bLoB = sb + B2LO_B + boff;
    int gid = lane >> 2, tg = lane & 3;

    int t = blockIdx.x;
    uint4 buf[4];
    if (t < NTILES) load_Ab_regs(buf, A, t * 64, tid);

    for (; t < NTILES; t += GEMM_GRID) {
        int r0 = t * 64;
        __syncthreads();

#pragma unroll
        for (int i = 0; i < 4; i++) {
            int idx = tid + i * 256;
            int row = idx >> 4;
            int c8 = (idx & 15) * 8;
            *(uint4*)(smem + (row * TSTRIDE + c8) * 2) = buf[i];
        }
        __syncthreads();

        int tn = t + GEMM_GRID;
        if (tn < NTILES) load_Ab_regs(buf, A, tn * 64, tid);

        float acc[2][4][4];
#pragma unroll
        for (int mi = 0; mi < 2; mi++)
#pragma unroll
            for (int nj = 0; nj < 4; nj++)
#pragma unroll
                for (int q = 0; q < 4; q++) acc[mi][nj][q] = 0.f;

#pragma unroll
        for (int kt = 0; kt < 8; kt++) {
            uint32_t ka = kt * 32;
            uint32_t ah[2][4], bh[4][2], bl[4][2];
#pragma unroll
            for (int mi = 0; mi < 2; mi++) {
                uint32_t d = mi * (16 * TSTRIDE * 2) + ka;
                LDSM_X4(ah[mi][0], ah[mi][1], ah[mi][2], ah[mi][3], aB + d);
            }
#pragma unroll
            for (int nj = 0; nj < 4; nj++) {
                uint32_t d = nj * (8 * TSTRIDE * 2) + ka;
                LDSM_X2(bh[nj][0], bh[nj][1], bHiB + d);
                LDSM_X2(bl[nj][0], bl[nj][1], bLoB + d);
            }
#pragma unroll
            for (int mi = 0; mi < 2; mi++)
#pragma unroll
                for (int nj = 0; nj < 4; nj++) {
                    MMA_BF16(acc[mi][nj], ah[mi], bh[nj]);
                    MMA_BF16(acc[mi][nj], ah[mi], bl[nj]);
                }
        }

#pragma unroll
        for (int mi = 0; mi < 2; mi++) {
            int r = r0 + warpRow * 32 + mi * 16 + gid;
            float dA = (r < NN) ? g_dinv[r] : 0.f;
            float dB = (r + 8 < NN) ? g_dinv[r + 8] : 0.f;
#pragma unroll
            for (int nj = 0; nj < 4; nj++) {
                int cb = warpCol * 32 + nj * 8 + tg * 2;
                if (r < NN) {
                    __nv_bfloat162 v;
                    v.x = __float2bfloat16_rn(dA * acc[mi][nj][0]);
                    v.y = __float2bfloat16_rn(dA * acc[mi][nj][1]);
                    *(__nv_bfloat162*)(C + (size_t)r * FD + cb) = v;
                }
                if (r + 8 < NN) {
                    __nv_bfloat162 v;
                    v.x = __float2bfloat16_rn(dB * acc[mi][nj][2]);
                    v.y = __float2bfloat16_rn(dB * acc[mi][nj][3]);
                    *(__nv_bfloat162*)(C + (size_t)(r + 8) * FD + cb) = v;
                }
            }
        }
    }
}

// ---------------- CSR build ----------------
__global__ void k_hist(const int4* __restrict__ dst4) {
    int e4 = blockIdx.x * blockDim.x + threadIdx.x;
    if (e4 >= NE / 4) return;
    int4 d = dst4[e4];
    atomicAdd(&g_count[d.x], 1);
    atomicAdd(&g_count[d.y], 1);
    atomicAdd(&g_count[d.z], 1);
    atomicAdd(&g_count[d.w], 1);
}

__global__ void k_scanA() {
    __shared__ int sh[SCAN_BLK];
    int i = blockIdx.x * SCAN_BLK + threadIdx.x;
    int v = (i < NN) ? g_count[i] : 0;
    if (i < NN) g_dinv[i] = rsqrtf((float)(v + 1));   // +1 self-loop
    sh[threadIdx.x] = v;
    __syncthreads();
    for (int off = SCAN_BLK / 2; off > 0; off >>= 1) {
        if (threadIdx.x < off) sh[threadIdx.x] += sh[threadIdx.x + off];
        __syncthreads();
    }
    if (threadIdx.x == 0) g_bsum[blockIdx.x] = sh[0];
}

__global__ void k_scanB() {
    __shared__ int sh[NSCAN];
    if (threadIdx.x < NSCAN) sh[threadIdx.x] = g_bsum[threadIdx.x];
    __syncthreads();
    if (threadIdx.x == 0) {
        int run = 0;
        for (int b = 0; b < NSCAN; b++) { int t = sh[b]; sh[b] = run; run += t; }
        g_rowptr[NN] = run;
    }
    __syncthreads();
    if (threadIdx.x < NSCAN) g_boff[threadIdx.x] = sh[threadIdx.x];
}

__global__ void k_scanC() {
    __shared__ int sh[SCAN_BLK];
    int i = blockIdx.x * SCAN_BLK + threadIdx.x;
    int v = (i < NN) ? g_count[i] : 0;
    sh[threadIdx.x] = v;
    __syncthreads();
    for (int off = 1; off < SCAN_BLK; off <<= 1) {
        int t = (threadIdx.x >= off) ? sh[threadIdx.x - off] : 0;
        __syncthreads();
        sh[threadIdx.x] += t;
        __syncthreads();
    }
    if (i < NN) {
        int excl = sh[threadIdx.x] - v + g_boff[blockIdx.x];
        g_rowptr[i] = excl;
        g_cursor[i] = excl;
    }
}

__global__ void k_fill(const int4* __restrict__ src4, const int4* __restrict__ dst4) {
    int e4 = blockIdx.x * blockDim.x + threadIdx.x;
    if (e4 >= NE / 4) return;
    int4 s = src4[e4];
    int4 d = dst4[e4];
    int ss[4] = {s.x, s.y, s.z, s.w};
    int dd[4] = {d.x, d.y, d.z, d.w};
#pragma unroll
    for (int q = 0; q < 4; q++) {
        int idx = atomicAdd(&g_cursor[dd[q]], 1);
        g_csrs[idx] = ss[q];
    }
}

// ---------------- agg + bias + LN + ReLU core (weightless sum over scaled rows) -------------
__device__ __forceinline__ float4 agg_ln_core(const __nv_bfloat16* __restrict__ h,
                                              const float* __restrict__ bias,
                                              const float* __restrict__ gamma,
                                              const float* __restrict__ beta,
                                              int node, int lane) {
    int c0 = lane * 4;
    float4 hv = ldbf4(h + (size_t)node * FD + c0);   // self row (already dinv-scaled)
    float ax = hv.x, ay = hv.y, az = hv.z, aw = hv.w;

    int e   = g_rowptr[node];
    int end = g_rowptr[node + 1];
    for (; e + 8 <= end; e += 8) {
        int p[8];
#pragma unroll
        for (int q = 0; q < 8; q++) p[q] = __ldcs(&g_csrs[e + q]);
        float4 v_[8];
#pragma unroll
        for (int q = 0; q < 8; q++) v_[q] = ldbf4(h + (size_t)p[q] * FD + c0);
#pragma unroll
        for (int q = 0; q < 8; q++) {
            ax += v_[q].x; ay += v_[q].y; az += v_[q].z; aw += v_[q].w;
        }
    }
    for (; e + 2 <= end; e += 2) {
        int p0 = __ldcs(&g_csrs[e]), p1 = __ldcs(&g_csrs[e + 1]);
        float4 v0 = ldbf4(h + (size_t)p0 * FD + c0);
        float4 v1 = ldbf4(h + (size_t)p1 * FD + c0);
        ax += v0.x + v1.x; ay += v0.y + v1.y;
        az += v0.z + v1.z; aw += v0.w + v1.w;
    }
    if (e < end) {
        int p = __ldcs(&g_csrs[e]);
        float4 v = ldbf4(h + (size_t)p * FD + c0);
        ax += v.x; ay += v.y; az += v.z; aw += v.w;
    }

    float dn = g_dinv[node];
    float4 b4 = *(const float4*)(bias + c0);
    float xx = dn * ax + b4.x, xy = dn * ay + b4.y;
    float xz = dn * az + b4.z, xw = dn * aw + b4.w;

    float s = xx + xy + xz + xw;
#pragma unroll
    for (int o = 16; o > 0; o >>= 1) s += __shfl_xor_sync(0xffffffffu, s, o);
    float mean = s * (1.f / FD);
    float dx = xx - mean, dy = xy - mean, dz = xz - mean, dw = xw - mean;
    float ss = dx * dx + dy * dy + dz * dz + dw * dw;
#pragma unroll
    for (int o = 16; o > 0; o >>= 1) ss += __shfl_xor_sync(0xffffffffu, ss, o);
    float inv = rsqrtf(ss * (1.f / FD) + LN_EPS);

    float4 g4  = *(const float4*)(gamma + c0);
    float4 be4 = *(const float4*)(beta + c0);
    float4 y;
    y.x = fmaxf(dx * inv * g4.x + be4.x, 0.f);
    y.y = fmaxf(dy * inv * g4.y + be4.y, 0.f);
    y.z = fmaxf(dz * inv * g4.z + be4.z, 0.f);
    y.w = fmaxf(dw * inv * g4.w + be4.w, 0.f);
    return y;
}

// ---------------- layer-1 aggregation (writes 128-dim y, bf16) ----------------
__global__ void __launch_bounds__(512) k_agg_ln(const __nv_bfloat16* __restrict__ h,
                                                const float* __restrict__ bias,
                                                const float* __restrict__ gamma,
                                                const float* __restrict__ beta,
                                                __nv_bfloat16* __restrict__ out) {
    int gw = (blockIdx.x * blockDim.x + threadIdx.x) >> 5;
    if (gw >= NN) return;
    int lane = threadIdx.x & 31;
    float4 y = agg_ln_core(h, bias, gamma, beta, gw, lane);
    __nv_bfloat162 p0 = __floats2bfloat162_rn(y.x, y.y);
    __nv_bfloat162 p1 = __floats2bfloat162_rn(y.z, y.w);
    uint2 packed;
    packed.x = *reinterpret_cast<uint32_t*>(&p0);
    packed.y = *reinterpret_cast<uint32_t*>(&p1);
    *(uint2*)(out + (size_t)gw * FD + lane * 4) = packed;
}

// ---------------- layer-2 agg + projection — persistent, writes dinv-scaled h3 -------------
__global__ void __launch_bounds__(256) k_agg_ln_proj(const __nv_bfloat16* __restrict__ h,
                                                     const float* __restrict__ bias,
                                                     const float* __restrict__ gamma,
                                                     const float* __restrict__ beta,
                                                     const float* __restrict__ W3,
                                                     float* __restrict__ h3out) {
    __shared__ float Ws[FD * NC];          // 20 KB, staged ONCE per CTA
    __shared__ float rbuf[8][FD];          // 4 KB
    int tid = threadIdx.x;
    for (int i = tid; i < FD * NC; i += 256) Ws[i] = W3[i];
    __syncthreads();

    int lane = tid & 31;
    int wslot = tid >> 5;
    int c1 = 32 + (lane & 7);

    for (int base = blockIdx.x * 8; base < NN; base += AGG3_GRID * 8) {
        int gw = base + wslot;
        if (gw < NN) {
            float4 y = agg_ln_core(h, bias, gamma, beta, gw, lane);

            *(float4*)&rbuf[wslot][lane * 4] = y;
            __syncwarp();

            float acc0 = 0.f, acc1 = 0.f;
#pragma unroll
            for (int k = 0; k < FD; k++) {
                float xk = rbuf[wslot][k];
                acc0 = fmaf(xk, Ws[k * NC + lane], acc0);
                acc1 = fmaf(xk, Ws[k * NC + c1], acc1);
            }
            float dn = g_dinv[gw];
            h3out[(size_t)gw * NC + lane] = dn * acc0;
            if (lane < 8) h3out[(size_t)gw * NC + 32 + lane] = dn * acc1;
            __syncwarp();
        }
    }
}

// ---------------- output aggregation + bias + log_softmax (weightless sum) ----------------
__global__ void __launch_bounds__(512) k_agg_out(const float* __restrict__ h3,
                                                 const float* __restrict__ b3,
                                                 float* __restrict__ out) {
    int gw = (blockIdx.x * blockDim.x + threadIdx.x) >> 5;
    if (gw >= NN) return;
    int lane = threadIdx.x & 31;
    int node = gw;
    bool hi = lane < (NC - 32);
    int c1 = 32 + (lane & 7);

    float a0 = __ldg(&h3[(size_t)node * NC + lane]);   // self row, already scaled
    float a1 = __ldg(&h3[(size_t)node * NC + c1]);

    int e   = g_rowptr[node];
    int end = g_rowptr[node + 1];
    for (; e + 4 <= end; e += 4) {
        int p[4];
#pragma unroll
        for (int q = 0; q < 4; q++) p[q] = __ldcs(&g_csrs[e + q]);
#pragma unroll
        for (int q = 0; q < 4; q++) {
            a0 += __ldg(&h3[(size_t)p[q] * NC + lane]);
            a1 += __ldg(&h3[(size_t)p[q] * NC + c1]);
        }
    }
    for (; e < end; e++) {
        int p = __ldcs(&g_csrs[e]);
        a0 += __ldg(&h3[(size_t)p * NC + lane]);
        a1 += __ldg(&h3[(size_t)p * NC + c1]);
    }

    float dn = g_dinv[node];
    float x0 = dn * a0 + b3[lane];
    float x1 = hi ? (dn * a1 + b3[32 + lane]) : -1e30f;

    float m = fmaxf(x0, x1);
#pragma unroll
    for (int o = 16; o > 0; o >>= 1) m = fmaxf(m, __shfl_xor_sync(0xffffffffu, m, o));
    float se = __expf(x0 - m) + (hi ? __expf(x1 - m) : 0.f);
#pragma unroll
    for (int o = 16; o > 0; o >>= 1) se += __shfl_xor_sync(0xffffffffu, se, o);
    float L = m + __logf(se);

    out[(size_t)node * NC + lane] = x0 - L;
    if (hi) out[(size_t)node * NC + 32 + lane] = x1 - L;
}

// ---------------- launch ----------------
extern "C" void kernel_launch(void* const* d_in, const int* in_sizes, int n_in,
                              void* d_out, int out_size) {
    const float* x    = (const float*)d_in[0];
    const int*   ei   = (const int*)d_in[1];
    const float* W1   = (const float*)d_in[2];
    const float* b1   = (const float*)d_in[3];
    const float* g1   = (const float*)d_in[4];
    const float* be1  = (const float*)d_in[5];
    const float* W2   = (const float*)d_in[6];
    const float* b2   = (const float*)d_in[7];
    const float* g2   = (const float*)d_in[8];
    const float* be2  = (const float*)d_in[9];
    const float* W3   = (const float*)d_in[10];
    const float* b3   = (const float*)d_in[11];
    float* out = (float*)d_out;

    const int4* src4 = (const int4*)ei;
    const int4* dst4 = (const int4*)(ei + NE);

    float *h3;
    __nv_bfloat16 *hAb, *hBb, *w1h, *w1l, *w2h, *w2l;
    cudaGetSymbolAddress((void**)&hAb, g_hAb);
    cudaGetSymbolAddress((void**)&hBb, g_hBb);
    cudaGetSymbolAddress((void**)&h3, g_h3);
    cudaGetSymbolAddress((void**)&w1h, g_W1hi);
    cudaGetSymbolAddress((void**)&w1l, g_W1lo);
    cudaGetSymbolAddress((void**)&w2h, g_W2hi);
    cudaGetSymbolAddress((void**)&w2l, g_W2lo);
    (void)n_in; (void)in_sizes; (void)out_size;

    cudaFuncSetAttribute(k_gemm_tc, cudaFuncAttributeMaxDynamicSharedMemorySize, GM_SMEM);
    cudaFuncSetAttribute(k_gemm_tc_b, cudaFuncAttributeMaxDynamicSharedMemorySize, GM_SMEM2);

    int tE4 = (NE / 4 + 255) / 256;
    int gWarp16 = (NN * 32 + 511) / 512;
    int gSetup = (NN + 255) / 256;

    // 11 launches; hist+scanA precede gemm1 (epilogue consumes dinv)
    k_setup<<<gSetup, 256>>>(W1, W2);
    k_hist<<<tE4, 256>>>(dst4);
    k_scanA<<<NSCAN, SCAN_BLK>>>();
    k_gemm_tc<<<GEMM_GRID, 256, GM_SMEM>>>(x, w1h, w1l, hAb);
    k_scanB<<<1, 128>>>();
    k_scanC<<<NSCAN, SCAN_BLK>>>();
    k_fill<<<tE4, 256>>>(src4, dst4);

    // layer 1 aggregation
    k_agg_ln<<<gWarp16, 512>>>(hAb, b1, g1, be1, hBb);
    // layer 2 gemm (bf16 input, 2-pass, scaled epilogue)
    k_gemm_tc_b<<<GEMM_GRID, 256, GM_SMEM2>>>(hBb, w2h, w2l, hAb);
    // layer 2 aggregation fused with projection (scaled h3 out)
    k_agg_ln_proj<<<AGG3_GRID, 256>>>(hAb, b2, g2, be2, W3, h3);
    // output aggregation + log_softmax
    k_agg_out<<<gWarp16, 512>>>(h3, b3, out);
}